// round 14
// baseline (speedup 1.0000x reference)
#include <cuda_runtime.h>
#include <cuda_bf16.h>
#include <cuda_fp16.h>
#include <math.h>
#include <stdint.h>

// ============================================================================
// SimpleAttn via mma.sync. split-bf16 3-MMA fp32 emulation (MLP/scores),
// fp16 1-MMA AV. Round 14: 512-thread 256x128 CTA tile (4 warps/SMSP),
// 2-stage pipeline; per-warp mainloop identical to R9. AV/softmax/prep = R13.
// B=8, N=2048, D_IN=512, H=1024, D_EMB=512, D_ATTN=256
// ============================================================================

#define B_   8
#define N_   2048
#define DIN  512
#define H_   1024
#define DEMB 512
#define DATT 256
#define M_   (B_ * N_)   // 16384

typedef __nv_bfloat16 bf16;

// ------------------------- device scratch (no allocs) ----------------------
__device__ __align__(16) bf16 g_xh[(size_t)M_ * DIN],           g_xl[(size_t)M_ * DIN];
__device__ __align__(16) bf16 g_W13Th[(size_t)(2*H_) * DIN],    g_W13Tl[(size_t)(2*H_) * DIN];
__device__ __align__(16) bf16 g_W24Th[(size_t)(2*DEMB) * H_],   g_W24Tl[(size_t)(2*DEMB) * H_];
__device__ __align__(16) float g_b13[2 * H_];
__device__ __align__(16) float g_b24[2 * DEMB];
__device__ __align__(16) bf16 g_hh[(size_t)M_ * 2 * H_],        g_hl[(size_t)M_ * 2 * H_];
__device__ __align__(16) __half g_eTh[(size_t)B_ * DEMB * N_];  // single fp16 embsT
__device__ __align__(16) bf16 g_kqh[(size_t)M_ * (2*DATT)],     g_kql[(size_t)M_ * (2*DATT)];
__device__ __align__(16) float g_scores[(size_t)B_ * N_ * N_];
__device__ __align__(16) __half g_Af[(size_t)B_ * N_ * N_];

// ------------------------- helpers -----------------------------------------
__device__ __forceinline__ uint32_t smem_u32(const void* p) {
    uint32_t a;
    asm("{ .reg .u64 t; cvta.to.shared.u64 t, %1; cvt.u32.u64 %0, t; }"
        : "=r"(a) : "l"(p));
    return a;
}

__device__ __forceinline__ uint32_t pack2(bf16 a, bf16 b) {
    return (uint32_t)__bfloat16_as_ushort(a) | ((uint32_t)__bfloat16_as_ushort(b) << 16);
}
__device__ __forceinline__ uint32_t pack2h(__half a, __half b) {
    return (uint32_t)__half_as_ushort(a) | ((uint32_t)__half_as_ushort(b) << 16);
}
__device__ __forceinline__ void split1(float v, bf16& h, bf16& l) {
    h = __float2bfloat16(v);
    l = __float2bfloat16(v - __bfloat162float(h));
}

#define LDSM4(r0, r1, r2, r3, addr) \
    asm volatile("ldmatrix.sync.aligned.m8n8.x4.shared.b16 {%0,%1,%2,%3}, [%4];" \
        : "=r"(r0), "=r"(r1), "=r"(r2), "=r"(r3) : "r"(addr))

__device__ __forceinline__ void mma16816(float* d, const uint32_t* a, const uint32_t* b) {
    asm volatile(
        "mma.sync.aligned.m16n8k16.row.col.f32.bf16.bf16.f32 "
        "{%0,%1,%2,%3}, {%4,%5,%6,%7}, {%8,%9}, {%0,%1,%2,%3};"
        : "+f"(d[0]), "+f"(d[1]), "+f"(d[2]), "+f"(d[3])
        : "r"(a[0]), "r"(a[1]), "r"(a[2]), "r"(a[3]), "r"(b[0]), "r"(b[1]));
}
__device__ __forceinline__ void mma16816h(float* d, const uint32_t* a, const uint32_t* b) {
    asm volatile(
        "mma.sync.aligned.m16n8k16.row.col.f32.f16.f16.f32 "
        "{%0,%1,%2,%3}, {%4,%5,%6,%7}, {%8,%9}, {%0,%1,%2,%3};"
        : "+f"(d[0]), "+f"(d[1]), "+f"(d[2]), "+f"(d[3])
        : "r"(a[0]), "r"(a[1]), "r"(a[2]), "r"(a[3]), "r"(b[0]), "r"(b[1]));
}

#define CP_ASYNC16(dst, src) \
    asm volatile("cp.async.cg.shared.global [%0], [%1], 16;" :: "r"(dst), "l"(src))
#define CP_COMMIT() asm volatile("cp.async.commit_group;" ::: "memory")

// generic tile loader: ROWS x 64 bf16, XOR swizzle, NT threads
template <int ROWS, int NT>
__device__ __forceinline__ void load_tile_t(const bf16* __restrict__ g, int ld,
                                            uint32_t sm, int tid) {
#pragma unroll
    for (int i = 0; i < (ROWS * 8) / NT; i++) {
        int idx = i * NT + tid;
        int r = idx >> 3;
        int c = idx & 7;
        const bf16* src = g + (size_t)r * ld + c * 8;
        uint32_t dst = sm + (uint32_t)(r * 128 + ((c ^ (r & 7)) << 4));
        CP_ASYNC16(dst, src);
    }
}

// 256-thread loader (AV kernel)
__device__ __forceinline__ void load_tile(const bf16* __restrict__ g, int ld,
                                          uint32_t sm, int tid) {
    load_tile_t<128, 256>(g, ld, sm, tid);
}

// big-tile stage layout: Ah(32K) Al(32K) Bh(16K) Bl(16K) = 96KB
#define BG_AL   32768
#define BG_BH   65536
#define BG_BL   81920
#define BG_STG  98304
#define SMEM_BG (2 * BG_STG)        // 196608, 1 CTA/SM, 512 threads
#define STAGE_AV 32768              // 2 tiles x 16KB (A + E single)
#define SMEM_AV  (3 * STAGE_AV)     // 98304, 2 CTAs/SM

// ============================================================================
// Split-bf16 GEMM (3-term), 256x128 CTA tile, 512 threads (4x4 warp grid),
// BK=64, 2-stage pipeline. Per-warp mainloop identical to R9.
// OMODE: 0 = split bf16 row-major; 2 = fp32 row-major (batch sC);
//        3 = bz==0 -> SINGLE fp16 transposed embsT; bz==1 -> split bf16 (ldc2)
// ============================================================================
template <int KITERS, bool RELU, bool HAS_BIAS, int OMODE>
__global__ __launch_bounds__(512, 1) void mma_gemm(
    const bf16* __restrict__ Ah, const bf16* __restrict__ Al, int lda, size_t sA,
    const bf16* __restrict__ Bh, const bf16* __restrict__ Bl, int ldb, size_t sB,
    const float* __restrict__ bias, int biasStride,
    void* outHi, void* outLo, int ldc, size_t sC,
    void* outHi2, void* outLo2, int ldc2)
{
    extern __shared__ char smem[];
    const uint32_t sbase = smem_u32(smem);
    const int tid = threadIdx.x;
    const int lane = tid & 31, w = tid >> 5;
    const int wm = w & 3, wn = w >> 2;          // 4 x 4 warp grid
    const int row0 = blockIdx.y * 256, col0 = blockIdx.x * 128, bz = blockIdx.z;

    const bf16* gAh = Ah + (size_t)bz * sA + (size_t)row0 * lda;
    const bf16* gAl = Al + (size_t)bz * sA + (size_t)row0 * lda;
    const bf16* gBh = Bh + (size_t)bz * sB + (size_t)col0 * ldb;
    const bf16* gBl = Bl + (size_t)bz * sB + (size_t)col0 * ldb;
    const float* biasB = HAS_BIAS ? (bias + (size_t)bz * biasStride) : bias;

    const int ra  = wm * 64 + (lane & 15);
    const int ca  = lane >> 4;
    const int rsa = ra & 7;
    const int rb  = wn * 32 + (lane & 7) + ((lane >> 4) & 1) * 8;
    const int cb  = (lane >> 3) & 1;
    const int rsb = rb & 7;

    float acc[4][4][4];
#pragma unroll
    for (int i = 0; i < 4; i++)
#pragma unroll
        for (int j = 0; j < 4; j++)
#pragma unroll
            for (int q = 0; q < 4; q++) acc[i][j][q] = 0.f;

    auto issue = [&](int s, int kt) {
        const size_t ko = (size_t)kt * 64;
        const uint32_t sb = sbase + s * BG_STG;
        load_tile_t<256, 512>(gAh + ko, lda, sb,         tid);
        load_tile_t<256, 512>(gAl + ko, lda, sb + BG_AL, tid);
        load_tile_t<128, 512>(gBh + ko, ldb, sb + BG_BH, tid);
        load_tile_t<128, 512>(gBl + ko, ldb, sb + BG_BL, tid);
        CP_COMMIT();
    };

    issue(0, 0);
    issue(1, 1);

    for (int kt = 0; kt < KITERS; kt++) {
        if (kt + 1 < KITERS) asm volatile("cp.async.wait_group 1;" ::: "memory");
        else                 asm volatile("cp.async.wait_group 0;" ::: "memory");
        __syncthreads();
        const uint32_t sb  = sbase + (kt & 1) * BG_STG;
        const uint32_t aHb = sb, aLb = sb + BG_AL, bHb = sb + BG_BH, bLb = sb + BG_BL;

#pragma unroll
        for (int ks = 0; ks < 4; ks++) {
            uint32_t ah[4][4], alr[4][4], bh[2][4], blr[2][4];
#pragma unroll
            for (int i = 0; i < 4; i++) {
                uint32_t off = (uint32_t)((ra + i * 16) * 128 +
                               ((((ks << 1) | ca) ^ rsa) << 4));
                LDSM4(ah[i][0],  ah[i][1],  ah[i][2],  ah[i][3],  aHb + off);
                LDSM4(alr[i][0], alr[i][1], alr[i][2], alr[i][3], aLb + off);
            }
#pragma unroll
            for (int jp = 0; jp < 2; jp++) {
                uint32_t off = (uint32_t)((rb + jp * 16) * 128 +
                               ((((ks << 1) | cb) ^ rsb) << 4));
                LDSM4(bh[jp][0],  bh[jp][1],  bh[jp][2],  bh[jp][3],  bHb + off);
                LDSM4(blr[jp][0], blr[jp][1], blr[jp][2], blr[jp][3], bLb + off);
            }
#pragma unroll
            for (int i = 0; i < 4; i++)
#pragma unroll
                for (int j = 0; j < 4; j++) {
                    const uint32_t* bph = &bh[j >> 1][(j & 1) << 1];
                    const uint32_t* bpl = &blr[j >> 1][(j & 1) << 1];
                    mma16816(acc[i][j], ah[i], bph);
                    mma16816(acc[i][j], ah[i], bpl);
                    mma16816(acc[i][j], alr[i], bph);
                }
        }
        __syncthreads();                       // stage fully consumed
        if (kt + 2 < KITERS) issue(kt & 1, kt + 2);
    }

    // ---------------- epilogue --------------------------------------------
    const bool rowmajor = (OMODE == 0) || (OMODE == 2) || (OMODE == 3 && bz == 1);
    if (rowmajor) {
        const int ldcs = (OMODE == 3) ? ldc2 : ldc;
        bf16* OH = (bf16*)((OMODE == 3) ? outHi2 : outHi);
        bf16* OL = (bf16*)((OMODE == 3) ? outLo2 : outLo);
#pragma unroll
        for (int j = 0; j < 4; j++) {
            const int cbj = col0 + wn * 32 + j * 8 + ((lane & 3) << 1);
            const float bb0 = HAS_BIAS ? biasB[cbj] : 0.f;
            const float bb1 = HAS_BIAS ? biasB[cbj + 1] : 0.f;
#pragma unroll
            for (int i = 0; i < 4; i++)
#pragma unroll
                for (int rep = 0; rep < 2; rep++) {
                    const int rg = row0 + wm * 64 + i * 16 + (lane >> 2) + rep * 8;
                    float v0 = acc[i][j][rep * 2 + 0] + bb0;
                    float v1 = acc[i][j][rep * 2 + 1] + bb1;
                    if (RELU) { v0 = fmaxf(v0, 0.f); v1 = fmaxf(v1, 0.f); }
                    if (OMODE == 2) {
                        float2* p = (float2*)((float*)outHi + (size_t)bz * sC +
                                              (size_t)rg * ldc + cbj);
                        *p = make_float2(v0, v1);
                    } else {
                        bf16 h0, l0, h1, l1;
                        split1(v0, h0, l0); split1(v1, h1, l1);
                        *(uint32_t*)(OH + (size_t)rg * ldcs + cbj) = pack2(h0, h1);
                        *(uint32_t*)(OL + (size_t)rg * ldcs + cbj) = pack2(l0, l1);
                    }
                }
        }
    } else {
        // transposed SINGLE fp16 embsT write: stage warp 64x32 tile, uint4 runs
        __syncthreads();
        float* buf = reinterpret_cast<float*>(smem) + w * 2112;   // 64 x 33
#pragma unroll
        for (int i = 0; i < 4; i++)
#pragma unroll
            for (int j = 0; j < 4; j++)
#pragma unroll
                for (int rep = 0; rep < 2; rep++) {
                    const int ml = i * 16 + (lane >> 2) + rep * 8;
                    const int nl = j * 8 + ((lane & 3) << 1);
                    buf[ml * 33 + nl]     = acc[i][j][rep * 2 + 0];
                    buf[ml * 33 + nl + 1] = acc[i][j][rep * 2 + 1];
                }
        __syncwarp();
        const int colsel = lane >> 3;
        const int seg    = lane & 7;
        const int rowg0 = row0 + wm * 64;
        const int b = rowg0 >> 11, pos = rowg0 & (N_ - 1);
        __half* OH = (__half*)outHi;
#pragma unroll
        for (int cp = 0; cp < 8; cp++) {
            const int csub = cp * 4 + colsel;
            const int colg = col0 + wn * 32 + csub;
            const float fb = HAS_BIAS ? biasB[colg] : 0.f;
            uint32_t ph[4];
#pragma unroll
            for (int q = 0; q < 4; q++) {
                float v0 = buf[(seg * 8 + 2 * q) * 33 + csub] + fb;
                float v1 = buf[(seg * 8 + 2 * q + 1) * 33 + csub] + fb;
                if (RELU) { v0 = fmaxf(v0, 0.f); v1 = fmaxf(v1, 0.f); }
                ph[q] = pack2h(__float2half_rn(v0), __float2half_rn(v1));
            }
            const size_t addr = ((size_t)b * DEMB + colg) * (size_t)N_ + pos + seg * 8;
            *(uint4*)(OH + addr) = make_uint4(ph[0], ph[1], ph[2], ph[3]);
        }
    }
}

// ============================================================================
// AV GEMM, fp16 1-term, 3-stage, 2 CTAs/SM (exactly R13).
// ============================================================================
template <int KITERS>
__global__ __launch_bounds__(256, 2) void mma_av(
    const __half* __restrict__ Af, int lda, size_t sA,
    const __half* __restrict__ Bh, int ldb, size_t sB,
    float* __restrict__ out, int ldc, size_t sC)
{
    extern __shared__ char smem[];
    const uint32_t sbase = smem_u32(smem);
    const int tid = threadIdx.x;
    const int lane = tid & 31, w = tid >> 5;
    const int wm = w & 1, wn = w >> 1;
    const int row0 = blockIdx.y * 128, col0 = blockIdx.x * 128, bz = blockIdx.z;

    const bf16* gA  = (const bf16*)(Af + (size_t)bz * sA + (size_t)row0 * lda);
    const bf16* gBh = (const bf16*)(Bh + (size_t)bz * sB + (size_t)col0 * ldb);

    const int ra  = wm * 64 + (lane & 15);
    const int ca  = lane >> 4;
    const int rsa = ra & 7;
    const int rb  = wn * 32 + (lane & 7) + ((lane >> 4) & 1) * 8;
    const int cb  = (lane >> 3) & 1;
    const int rsb = rb & 7;

    float acc[4][4][4];
#pragma unroll
    for (int i = 0; i < 4; i++)
#pragma unroll
        for (int j = 0; j < 4; j++)
#pragma unroll
            for (int q = 0; q < 4; q++) acc[i][j][q] = 0.f;

    auto issue = [&](int s, int kt) {
        const size_t ko = (size_t)kt * 64;
        const uint32_t sb = sbase + s * STAGE_AV;
        load_tile(gA  + ko, lda, sb,         tid);
        load_tile(gBh + ko, ldb, sb + 16384, tid);
        CP_COMMIT();
    };

    issue(0, 0);
    issue(1, 1);

    for (int kt = 0; kt < KITERS; kt++) {
        if (kt + 1 < KITERS) asm volatile("cp.async.wait_group 1;" ::: "memory");
        else                 asm volatile("cp.async.wait_group 0;" ::: "memory");
        __syncthreads();
        if (kt + 2 < KITERS) issue((kt + 2) % 3, kt + 2);
        const uint32_t sb = sbase + (kt % 3) * STAGE_AV;
        const uint32_t aB = sb, bHb = sb + 16384;

#pragma unroll
        for (int ks = 0; ks < 4; ks++) {
            uint32_t ah[4][4], bh[2][4];
#pragma unroll
            for (int i = 0; i < 4; i++) {
                uint32_t off = (uint32_t)((ra + i * 16) * 128 +
                               ((((ks << 1) | ca) ^ rsa) << 4));
                LDSM4(ah[i][0], ah[i][1], ah[i][2], ah[i][3], aB + off);
            }
#pragma unroll
            for (int jp = 0; jp < 2; jp++) {
                uint32_t off = (uint32_t)((rb + jp * 16) * 128 +
                               ((((ks << 1) | cb) ^ rsb) << 4));
                LDSM4(bh[jp][0], bh[jp][1], bh[jp][2], bh[jp][3], bHb + off);
            }
#pragma unroll
            for (int i = 0; i < 4; i++)
#pragma unroll
                for (int j = 0; j < 4; j++)
                    mma16816h(acc[i][j], ah[i], &bh[j >> 1][(j & 1) << 1]);
        }
    }

#pragma unroll
    for (int j = 0; j < 4; j++) {
        const int cbj = col0 + wn * 32 + j * 8 + ((lane & 3) << 1);
#pragma unroll
        for (int i = 0; i < 4; i++)
#pragma unroll
            for (int rep = 0; rep < 2; rep++) {
                const int rg = row0 + wm * 64 + i * 16 + (lane >> 2) + rep * 8;
                float2* p = (float2*)(out + (size_t)bz * sC + (size_t)rg * ldc + cbj);
                *p = make_float2(acc[i][j][rep * 2 + 0], acc[i][j][rep * 2 + 1]);
            }
    }
}

// ============================================================================
// prep kernels
// ============================================================================
__global__ __launch_bounds__(256) void k_split(const float* __restrict__ s,
                                               bf16* __restrict__ h,
                                               bf16* __restrict__ l, size_t n) {
    size_t i = ((size_t)blockIdx.x * 256 + threadIdx.x) * 4;
    if (i >= n) return;
    float4 v = *reinterpret_cast<const float4*>(s + i);
    bf16 h0, l0, h1, l1, h2, l2, h3, l3;
    split1(v.x, h0, l0); split1(v.y, h1, l1);
    split1(v.z, h2, l2); split1(v.w, h3, l3);
    *reinterpret_cast<uint2*>(h + i) = make_uint2(pack2(h0, h1), pack2(h2, h3));
    *reinterpret_cast<uint2*>(l + i) = make_uint2(pack2(l0, l1), pack2(l2, l3));
}

__global__ __launch_bounds__(256) void k_splitT_all(
    const float* __restrict__ We1, const float* __restrict__ Wk1,
    const float* __restrict__ We2, const float* __restrict__ Wk2,
    bf16* __restrict__ W13h, bf16* __restrict__ W13l,
    bf16* __restrict__ W24h, bf16* __restrict__ W24l)
{
    const int z = blockIdx.z;
    const float* W; bf16 *Th, *Tl; int K, Nc, nOff;
    if (z == 0)      { W = We1; Th = W13h; Tl = W13l; K = DIN; Nc = H_;       nOff = 0; }
    else if (z == 1) { W = Wk1; Th = W13h; Tl = W13l; K = DIN; Nc = H_;       nOff = H_; }
    else if (z == 2) { W = We2; Th = W24h; Tl = W24l; K = H_;  Nc = DEMB;     nOff = 0; }
    else             { W = Wk2; Th = W24h; Tl = W24l; K = H_;  Nc = 2 * DATT; nOff = DEMB; }
    const int k0 = blockIdx.x * 32, n0 = blockIdx.y * 32;
    if (k0 >= K || n0 >= Nc) return;

    __shared__ float t[32][33];
    const int c = threadIdx.x & 31, r = threadIdx.x >> 5;
#pragma unroll
    for (int i = 0; i < 4; i++)
        t[i * 8 + r][c] = W[(size_t)(k0 + i * 8 + r) * Nc + n0 + c];
    __syncthreads();
#pragma unroll
    for (int i = 0; i < 4; i++) {
        const int n = n0 + i * 8 + r;
        bf16 h, l;
        split1(t[c][i * 8 + r], h, l);
        Th[(size_t)(nOff + n) * K + k0 + c] = h;
        Tl[(size_t)(nOff + n) * K + k0 + c] = l;
    }
}

__global__ void k_biases(const float* __restrict__ be1, const float* __restrict__ bk1,
                         const float* __restrict__ be2, const float* __restrict__ bk2,
                         float* __restrict__ b13, float* __restrict__ b24) {
    int i = blockIdx.x * 256 + threadIdx.x;
    if (i < H_)                 b13[i] = be1[i];
    else if (i < 2 * H_)        b13[i] = bk1[i - H_];
    else if (i < 2 * H_ + DEMB) b24[i - 2 * H_] = be2[i - 2 * H_];
    else if (i < 2 * H_ + 2 * DEMB) b24[i - 2 * H_] = bk2[i - 2 * H_ - DEMB];
}

// ============================================================================
// softmax over rows of scores (fp32), output single fp16
// ============================================================================
__global__ __launch_bounds__(256) void k_softmax(const float* __restrict__ S,
                                                 __half* __restrict__ Af) {
    const size_t row = blockIdx.x;
    const float4* r = reinterpret_cast<const float4*>(S + row * N_);
    const int tid = threadIdx.x;
    __shared__ float red[256];

    float4 a = r[tid], b = r[tid + 256];
    float m = fmaxf(fmaxf(fmaxf(a.x, a.y), fmaxf(a.z, a.w)),
                    fmaxf(fmaxf(b.x, b.y), fmaxf(b.z, b.w)));
    red[tid] = m; __syncthreads();
#pragma unroll
    for (int s = 128; s > 0; s >>= 1) {
        if (tid < s) red[tid] = fmaxf(red[tid], red[tid + s]);
        __syncthreads();
    }
    m = red[0]; __syncthreads();

    a.x = __expf(a.x - m); a.y = __expf(a.y - m);
    a.z = __expf(a.z - m); a.w = __expf(a.w - m);
    b.x = __expf(b.x - m); b.y = __expf(b.y - m);
    b.z = __expf(b.z - m); b.w = __expf(b.w - m);
    red[tid] = (a.x + a.y + a.z + a.w) + (b.x + b.y + b.z + b.w);
    __syncthreads();
#pragma unroll
    for (int s = 128; s > 0; s >>= 1) {
        if (tid < s) red[tid] += red[tid + s];
        __syncthreads();
    }
    const float inv = 1.f / red[0];

    uint32_t q0 = pack2h(__float2half_rn(a.x * inv), __float2half_rn(a.y * inv));
    uint32_t q1 = pack2h(__float2half_rn(a.z * inv), __float2half_rn(a.w * inv));
    uint32_t q2 = pack2h(__float2half_rn(b.x * inv), __float2half_rn(b.y * inv));
    uint32_t q3 = pack2h(__float2half_rn(b.z * inv), __float2half_rn(b.w * inv));
    uint2* o = reinterpret_cast<uint2*>(Af + row * N_);
    o[tid]       = make_uint2(q0, q1);
    o[tid + 256] = make_uint2(q2, q3);
}

// ============================================================================
extern "C" void kernel_launch(void* const* d_in, const int* in_sizes, int n_in,
                              void* d_out, int out_size)
{
    const float* x   = (const float*)d_in[0];
    const float* We1 = (const float*)d_in[1];
    const float* be1 = (const float*)d_in[2];
    const float* We2 = (const float*)d_in[3];
    const float* be2 = (const float*)d_in[4];
    const float* Wk1 = (const float*)d_in[5];
    const float* bk1 = (const float*)d_in[6];
    const float* Wk2 = (const float*)d_in[7];
    const float* bk2 = (const float*)d_in[8];
    float* out = (float*)d_out;

    bf16 *xh, *xl, *W13Th, *W13Tl, *W24Th, *W24Tl, *hh, *hl, *kqh, *kql;
    __half *eTh, *Af;
    float *scores, *b13, *b24;
    cudaGetSymbolAddress((void**)&xh, g_xh);       cudaGetSymbolAddress((void**)&xl, g_xl);
    cudaGetSymbolAddress((void**)&W13Th, g_W13Th); cudaGetSymbolAddress((void**)&W13Tl, g_W13Tl);
    cudaGetSymbolAddress((void**)&W24Th, g_W24Th); cudaGetSymbolAddress((void**)&W24Tl, g_W24Tl);
    cudaGetSymbolAddress((void**)&b13, g_b13);     cudaGetSymbolAddress((void**)&b24, g_b24);
    cudaGetSymbolAddress((void**)&hh, g_hh);       cudaGetSymbolAddress((void**)&hl, g_hl);
    cudaGetSymbolAddress((void**)&eTh, g_eTh);
    cudaGetSymbolAddress((void**)&kqh, g_kqh);     cudaGetSymbolAddress((void**)&kql, g_kql);
    cudaGetSymbolAddress((void**)&scores, g_scores);
    cudaGetSymbolAddress((void**)&Af, g_Af);

    cudaFuncSetAttribute(mma_gemm<8,  true,  true,  0>, cudaFuncAttributeMaxDynamicSharedMemorySize, SMEM_BG);
    cudaFuncSetAttribute(mma_gemm<16, false, true,  3>, cudaFuncAttributeMaxDynamicSharedMemorySize, SMEM_BG);
    cudaFuncSetAttribute(mma_gemm<4,  false, false, 2>, cudaFuncAttributeMaxDynamicSharedMemorySize, SMEM_BG);
    cudaFuncSetAttribute(mma_av<32>, cudaFuncAttributeMaxDynamicSharedMemorySize, SMEM_AV);

    // ---- prep (3 launches; skip-5 ncu capture lands on the scores GEMM) -----
    k_split<<<(M_ * DIN / 4 + 255) / 256, 256>>>(x, xh, xl, (size_t)M_ * DIN);
    k_splitT_all<<<dim3(32, 32, 4), 256>>>(We1, Wk1, We2, Wk2,
                                           W13Th, W13Tl, W24Th, W24Tl);
    k_biases<<<(2 * H_ + 2 * DEMB + 255) / 256, 256>>>(be1, bk1, be2, bk2, b13, b24);

    // ---- 1) h_all = relu(x @ [We1|Wk1] + [be1|bk1])   [16384 x 2048] --------
    mma_gemm<8, true, true, 0><<<dim3((2 * H_) / 128, M_ / 256, 1), 512, SMEM_BG>>>(
        xh, xl, DIN, 0, W13Th, W13Tl, DIN, 0, b13, 0,
        hh, hl, 2 * H_, 0, nullptr, nullptr, 0);

    // ---- 2+4 merged (z=0: embsT single fp16; z=1: kq bf16) -------------------
    mma_gemm<16, false, true, 3><<<dim3(DEMB / 128, M_ / 256, 2), 512, SMEM_BG>>>(
        hh, hl, 2 * H_, (size_t)H_,
        W24Th, W24Tl, H_, (size_t)DEMB * H_,
        b24, DEMB,
        eTh, nullptr, 0, 0,
        kqh, kql, 2 * DATT);

    // ---- 5) scores_b = Q_b @ K_b^T --------------------------------------------
    mma_gemm<4, false, false, 2><<<dim3(N_ / 128, N_ / 256, B_), 512, SMEM_BG>>>(
        kqh + DATT, kql + DATT, 2 * DATT, (size_t)N_ * 2 * DATT,
        kqh,        kql,        2 * DATT, (size_t)N_ * 2 * DATT,
        nullptr, 0, scores, nullptr, N_, (size_t)N_ * N_, nullptr, nullptr, 0);

    // ---- 6) softmax -> single fp16 A ------------------------------------------
    k_softmax<<<B_ * N_, 256>>>(scores, Af);

    // ---- 7) out_b = A_b @ embs_b  (fp16 1-term, 2 CTAs/SM) --------------------
    mma_av<32><<<dim3(DEMB / 128, N_ / 128, B_), 256, SMEM_AV>>>(
        Af, N_, (size_t)N_ * N_,
        eTh, N_, (size_t)DEMB * N_,
        out, DEMB, (size_t)N_ * DEMB);
}

// round 15
// speedup vs baseline: 1.0810x; 1.0810x over previous
#include <cuda_runtime.h>
#include <cuda_bf16.h>
#include <cuda_fp16.h>
#include <math.h>
#include <stdint.h>

// ============================================================================
// SimpleAttn via mma.sync. Round 15 (base = R13 best):
//  - GEMM1: bf16 3-term, also emits h_f (fp16) for embs path
//  - kq:    bf16 3-term (full precision for logits)
//  - embs:  fp16 2-term (h_f single x We2 fp16 hi/lo), occ 2  <-- new
//  - scores: bf16 3-term (R13); AV: fp16 1-term occ 2 (R13)
// B=8, N=2048, D_IN=512, H=1024, D_EMB=512, D_ATTN=256
// ============================================================================

#define B_   8
#define N_   2048
#define DIN  512
#define H_   1024
#define DEMB 512
#define DATT 256
#define M_   (B_ * N_)   // 16384

typedef __nv_bfloat16 bf16;

// ------------------------- device scratch (no allocs) ----------------------
__device__ __align__(16) bf16 g_xh[(size_t)M_ * DIN],           g_xl[(size_t)M_ * DIN];
__device__ __align__(16) bf16 g_W13Th[(size_t)(2*H_) * DIN],    g_W13Tl[(size_t)(2*H_) * DIN];
__device__ __align__(16) bf16 g_Wk2Th[(size_t)(2*DATT) * H_],   g_Wk2Tl[(size_t)(2*DATT) * H_];
__device__ __align__(16) __half g_We2fh[(size_t)DEMB * H_],     g_We2fl[(size_t)DEMB * H_];
__device__ __align__(16) float g_b13[2 * H_];
__device__ __align__(16) bf16 g_hh[(size_t)M_ * 2 * H_],        g_hl[(size_t)M_ * 2 * H_];
__device__ __align__(16) __half g_hf[(size_t)M_ * H_];          // fp16 h, embs half
__device__ __align__(16) __half g_eTh[(size_t)B_ * DEMB * N_];  // single fp16 embsT
__device__ __align__(16) bf16 g_kqh[(size_t)M_ * (2*DATT)],     g_kql[(size_t)M_ * (2*DATT)];
__device__ __align__(16) float g_scores[(size_t)B_ * N_ * N_];
__device__ __align__(16) __half g_Af[(size_t)B_ * N_ * N_];

// ------------------------- helpers -----------------------------------------
__device__ __forceinline__ uint32_t smem_u32(const void* p) {
    uint32_t a;
    asm("{ .reg .u64 t; cvta.to.shared.u64 t, %1; cvt.u32.u64 %0, t; }"
        : "=r"(a) : "l"(p));
    return a;
}

__device__ __forceinline__ uint32_t pack2(bf16 a, bf16 b) {
    return (uint32_t)__bfloat16_as_ushort(a) | ((uint32_t)__bfloat16_as_ushort(b) << 16);
}
__device__ __forceinline__ uint32_t pack2h(__half a, __half b) {
    return (uint32_t)__half_as_ushort(a) | ((uint32_t)__half_as_ushort(b) << 16);
}
__device__ __forceinline__ void split1(float v, bf16& h, bf16& l) {
    h = __float2bfloat16(v);
    l = __float2bfloat16(v - __bfloat162float(h));
}
__device__ __forceinline__ void split1h(float v, __half& h, __half& l) {
    h = __float2half_rn(v);
    l = __float2half_rn(v - __half2float(h));
}

#define LDSM4(r0, r1, r2, r3, addr) \
    asm volatile("ldmatrix.sync.aligned.m8n8.x4.shared.b16 {%0,%1,%2,%3}, [%4];" \
        : "=r"(r0), "=r"(r1), "=r"(r2), "=r"(r3) : "r"(addr))

__device__ __forceinline__ void mma16816(float* d, const uint32_t* a, const uint32_t* b) {
    asm volatile(
        "mma.sync.aligned.m16n8k16.row.col.f32.bf16.bf16.f32 "
        "{%0,%1,%2,%3}, {%4,%5,%6,%7}, {%8,%9}, {%0,%1,%2,%3};"
        : "+f"(d[0]), "+f"(d[1]), "+f"(d[2]), "+f"(d[3])
        : "r"(a[0]), "r"(a[1]), "r"(a[2]), "r"(a[3]), "r"(b[0]), "r"(b[1]));
}
__device__ __forceinline__ void mma16816h(float* d, const uint32_t* a, const uint32_t* b) {
    asm volatile(
        "mma.sync.aligned.m16n8k16.row.col.f32.f16.f16.f32 "
        "{%0,%1,%2,%3}, {%4,%5,%6,%7}, {%8,%9}, {%0,%1,%2,%3};"
        : "+f"(d[0]), "+f"(d[1]), "+f"(d[2]), "+f"(d[3])
        : "r"(a[0]), "r"(a[1]), "r"(a[2]), "r"(a[3]), "r"(b[0]), "r"(b[1]));
}

#define CP_ASYNC16(dst, src) \
    asm volatile("cp.async.cg.shared.global [%0], [%1], 16;" :: "r"(dst), "l"(src))
#define CP_COMMIT() asm volatile("cp.async.commit_group;" ::: "memory")

// tile loader: 128 rows x 64 x 2B, XOR swizzle (chunk c of row r at c ^ (r&7))
__device__ __forceinline__ void load_tile(const bf16* __restrict__ g, int ld,
                                          uint32_t sm, int tid) {
#pragma unroll
    for (int i = 0; i < 4; i++) {
        int idx = i * 256 + tid;
        int r = idx >> 3;
        int c = idx & 7;
        const bf16* src = g + (size_t)r * ld + c * 8;
        uint32_t dst = sm + (uint32_t)(r * 128 + ((c ^ (r & 7)) << 4));
        CP_ASYNC16(dst, src);
    }
}

#define STAGE_SZ 65536              // 4 tiles x 16KB
#define SMEM_SZ  (3 * STAGE_SZ)     // 196608, 1 CTA/SM
#define STAGE_AV 32768              // 2 tiles (A + E)
#define SMEM_AV  (3 * STAGE_AV)     // 98304, 2 CTAs/SM
#define STAGE_EM 49152              // 3 tiles (A, Bh, Bl)
#define SMEM_EM  (2 * STAGE_EM)     // 98304, 2 CTAs/SM

// ============================================================================
// Split-bf16 GEMM (3-term), BK=64, 3-stage, acc-major (R9-proven).
// OMODE: 0 = split bf16 row-major
//        2 = fp32 row-major (batch stride sC)
//        4 = split bf16 row-major + single fp16 to outF (cols < H_ only)
// ============================================================================
template <int KITERS, bool RELU, bool HAS_BIAS, int OMODE>
__global__ __launch_bounds__(256, 1) void mma_gemm(
    const bf16* __restrict__ Ah, const bf16* __restrict__ Al, int lda, size_t sA,
    const bf16* __restrict__ Bh, const bf16* __restrict__ Bl, int ldb, size_t sB,
    const float* __restrict__ bias,
    void* outHi, void* outLo, int ldc, size_t sC,
    __half* __restrict__ outF)
{
    extern __shared__ char smem[];
    const uint32_t sbase = smem_u32(smem);
    const int tid = threadIdx.x;
    const int lane = tid & 31, w = tid >> 5;
    const int wm = w & 1, wn = w >> 1;
    const int row0 = blockIdx.y * 128, col0 = blockIdx.x * 128, bz = blockIdx.z;

    const bf16* gAh = Ah + (size_t)bz * sA + (size_t)row0 * lda;
    const bf16* gAl = Al + (size_t)bz * sA + (size_t)row0 * lda;
    const bf16* gBh = Bh + (size_t)bz * sB + (size_t)col0 * ldb;
    const bf16* gBl = Bl + (size_t)bz * sB + (size_t)col0 * ldb;

    const int ra  = wm * 64 + (lane & 15);
    const int ca  = lane >> 4;
    const int rsa = ra & 7;
    const int rb  = wn * 32 + (lane & 7) + ((lane >> 4) & 1) * 8;
    const int cb  = (lane >> 3) & 1;
    const int rsb = rb & 7;

    float acc[4][4][4];
#pragma unroll
    for (int i = 0; i < 4; i++)
#pragma unroll
        for (int j = 0; j < 4; j++)
#pragma unroll
            for (int q = 0; q < 4; q++) acc[i][j][q] = 0.f;

    auto issue = [&](int s, int kt) {
        const size_t ko = (size_t)kt * 64;
        const uint32_t sb = sbase + s * STAGE_SZ;
        load_tile(gAh + ko, lda, sb,             tid);
        load_tile(gAl + ko, lda, sb + 16384,     tid);
        load_tile(gBh + ko, ldb, sb + 32768,     tid);
        load_tile(gBl + ko, ldb, sb + 49152,     tid);
        CP_COMMIT();
    };

    issue(0, 0);
    issue(1, 1);

    for (int kt = 0; kt < KITERS; kt++) {
        if (kt + 1 < KITERS) asm volatile("cp.async.wait_group 1;" ::: "memory");
        else                 asm volatile("cp.async.wait_group 0;" ::: "memory");
        __syncthreads();
        if (kt + 2 < KITERS) issue((kt + 2) % 3, kt + 2);
        const uint32_t sb  = sbase + (kt % 3) * STAGE_SZ;
        const uint32_t aHb = sb, aLb = sb + 16384, bHb = sb + 32768, bLb = sb + 49152;

#pragma unroll
        for (int ks = 0; ks < 4; ks++) {
            uint32_t ah[4][4], alr[4][4], bh[2][4], blr[2][4];
#pragma unroll
            for (int i = 0; i < 4; i++) {
                uint32_t off = (uint32_t)((ra + i * 16) * 128 +
                               ((((ks << 1) | ca) ^ rsa) << 4));
                LDSM4(ah[i][0],  ah[i][1],  ah[i][2],  ah[i][3],  aHb + off);
                LDSM4(alr[i][0], alr[i][1], alr[i][2], alr[i][3], aLb + off);
            }
#pragma unroll
            for (int jp = 0; jp < 2; jp++) {
                uint32_t off = (uint32_t)((rb + jp * 16) * 128 +
                               ((((ks << 1) | cb) ^ rsb) << 4));
                LDSM4(bh[jp][0],  bh[jp][1],  bh[jp][2],  bh[jp][3],  bHb + off);
                LDSM4(blr[jp][0], blr[jp][1], blr[jp][2], blr[jp][3], bLb + off);
            }
#pragma unroll
            for (int i = 0; i < 4; i++)
#pragma unroll
                for (int j = 0; j < 4; j++) {
                    const uint32_t* bph = &bh[j >> 1][(j & 1) << 1];
                    const uint32_t* bpl = &blr[j >> 1][(j & 1) << 1];
                    mma16816(acc[i][j], ah[i], bph);
                    mma16816(acc[i][j], ah[i], bpl);
                    mma16816(acc[i][j], alr[i], bph);
                }
        }
    }

    // ---------------- epilogue (row-major only) ----------------------------
#pragma unroll
    for (int j = 0; j < 4; j++) {
        const int cbj = col0 + wn * 32 + j * 8 + ((lane & 3) << 1);
        const float bb0 = HAS_BIAS ? bias[cbj] : 0.f;
        const float bb1 = HAS_BIAS ? bias[cbj + 1] : 0.f;
#pragma unroll
        for (int i = 0; i < 4; i++)
#pragma unroll
            for (int rep = 0; rep < 2; rep++) {
                const int rg = row0 + wm * 64 + i * 16 + (lane >> 2) + rep * 8;
                float v0 = acc[i][j][rep * 2 + 0] + bb0;
                float v1 = acc[i][j][rep * 2 + 1] + bb1;
                if (RELU) { v0 = fmaxf(v0, 0.f); v1 = fmaxf(v1, 0.f); }
                if (OMODE == 2) {
                    float2* p = (float2*)((float*)outHi + (size_t)bz * sC +
                                          (size_t)rg * ldc + cbj);
                    *p = make_float2(v0, v1);
                } else {
                    bf16 h0, l0, h1, l1;
                    split1(v0, h0, l0); split1(v1, h1, l1);
                    *(uint32_t*)((bf16*)outHi + (size_t)rg * ldc + cbj) = pack2(h0, h1);
                    *(uint32_t*)((bf16*)outLo + (size_t)rg * ldc + cbj) = pack2(l0, l1);
                    if (OMODE == 4 && cbj < H_) {
                        *(uint32_t*)(outF + (size_t)rg * H_ + cbj) =
                            pack2h(__float2half_rn(v0), __float2half_rn(v1));
                    }
                }
            }
    }
}

// ============================================================================
// embs GEMM: fp16 2-term (A = h_f single, B = We2 fp16 hi/lo), 2-stage,
// 2 CTAs/SM; transposed single-fp16 epilogue into embsT[b][DEMB][N_] + bias.
// ============================================================================
template <int KITERS>
__global__ __launch_bounds__(256, 2) void mma_embs(
    const __half* __restrict__ Af, int lda,
    const __half* __restrict__ Bh, const __half* __restrict__ Bl, int ldb,
    const float* __restrict__ bias,
    __half* __restrict__ outT)
{
    extern __shared__ char smem[];
    const uint32_t sbase = smem_u32(smem);
    const int tid = threadIdx.x;
    const int lane = tid & 31, w = tid >> 5;
    const int wm = w & 1, wn = w >> 1;
    const int row0 = blockIdx.y * 128, col0 = blockIdx.x * 128;

    const bf16* gA  = (const bf16*)(Af + (size_t)row0 * lda);
    const bf16* gBh = (const bf16*)(Bh + (size_t)col0 * ldb);
    const bf16* gBl = (const bf16*)(Bl + (size_t)col0 * ldb);

    const int ra  = wm * 64 + (lane & 15);
    const int ca  = lane >> 4;
    const int rsa = ra & 7;
    const int rb  = wn * 32 + (lane & 7) + ((lane >> 4) & 1) * 8;
    const int cb  = (lane >> 3) & 1;
    const int rsb = rb & 7;

    float acc[4][4][4];
#pragma unroll
    for (int i = 0; i < 4; i++)
#pragma unroll
        for (int j = 0; j < 4; j++)
#pragma unroll
            for (int q = 0; q < 4; q++) acc[i][j][q] = 0.f;

    auto issue = [&](int s, int kt) {
        const size_t ko = (size_t)kt * 64;
        const uint32_t sb = sbase + s * STAGE_EM;
        load_tile(gA  + ko, lda, sb,         tid);
        load_tile(gBh + ko, ldb, sb + 16384, tid);
        load_tile(gBl + ko, ldb, sb + 32768, tid);
        CP_COMMIT();
    };

    issue(0, 0);
    issue(1, 1);

    for (int kt = 0; kt < KITERS; kt++) {
        if (kt + 1 < KITERS) asm volatile("cp.async.wait_group 1;" ::: "memory");
        else                 asm volatile("cp.async.wait_group 0;" ::: "memory");
        __syncthreads();
        const uint32_t sb  = sbase + (kt & 1) * STAGE_EM;
        const uint32_t aB = sb, bHb = sb + 16384, bLb = sb + 32768;

#pragma unroll
        for (int ks = 0; ks < 4; ks++) {
            uint32_t ah[4][4], bh[2][4], blr[2][4];
#pragma unroll
            for (int i = 0; i < 4; i++) {
                uint32_t off = (uint32_t)((ra + i * 16) * 128 +
                               ((((ks << 1) | ca) ^ rsa) << 4));
                LDSM4(ah[i][0], ah[i][1], ah[i][2], ah[i][3], aB + off);
            }
#pragma unroll
            for (int jp = 0; jp < 2; jp++) {
                uint32_t off = (uint32_t)((rb + jp * 16) * 128 +
                               ((((ks << 1) | cb) ^ rsb) << 4));
                LDSM4(bh[jp][0],  bh[jp][1],  bh[jp][2],  bh[jp][3],  bHb + off);
                LDSM4(blr[jp][0], blr[jp][1], blr[jp][2], blr[jp][3], bLb + off);
            }
#pragma unroll
            for (int i = 0; i < 4; i++)
#pragma unroll
                for (int j = 0; j < 4; j++) {
                    mma16816h(acc[i][j], ah[i], &bh[j >> 1][(j & 1) << 1]);
                    mma16816h(acc[i][j], ah[i], &blr[j >> 1][(j & 1) << 1]);
                }
        }
        __syncthreads();                 // stage kt&1 fully consumed
        if (kt + 2 < KITERS) issue(kt & 1, kt + 2);
    }

    // transposed single fp16 write (R13-proven pattern), with bias, no relu
    float* buf = reinterpret_cast<float*>(smem) + w * 2112;   // 64 x 33
#pragma unroll
    for (int i = 0; i < 4; i++)
#pragma unroll
        for (int j = 0; j < 4; j++)
#pragma unroll
            for (int rep = 0; rep < 2; rep++) {
                const int ml = i * 16 + (lane >> 2) + rep * 8;
                const int nl = j * 8 + ((lane & 3) << 1);
                buf[ml * 33 + nl]     = acc[i][j][rep * 2 + 0];
                buf[ml * 33 + nl + 1] = acc[i][j][rep * 2 + 1];
            }
    __syncwarp();
    const int colsel = lane >> 3;
    const int seg    = lane & 7;
    const int rowg0 = row0 + wm * 64;
    const int b = rowg0 >> 11, pos = rowg0 & (N_ - 1);
#pragma unroll
    for (int cp = 0; cp < 8; cp++) {
        const int csub = cp * 4 + colsel;
        const int colg = col0 + wn * 32 + csub;
        const float fb = bias[colg];
        uint32_t ph[4];
#pragma unroll
        for (int q = 0; q < 4; q++) {
            float v0 = buf[(seg * 8 + 2 * q) * 33 + csub] + fb;
            float v1 = buf[(seg * 8 + 2 * q + 1) * 33 + csub] + fb;
            ph[q] = pack2h(__float2half_rn(v0), __float2half_rn(v1));
        }
        const size_t addr = ((size_t)b * DEMB + colg) * (size_t)N_ + pos + seg * 8;
        *(uint4*)(outT + addr) = make_uint4(ph[0], ph[1], ph[2], ph[3]);
    }
}

// ============================================================================
// AV GEMM, fp16 1-term, 3-stage, 2 CTAs/SM (exactly R13).
// ============================================================================
template <int KITERS>
__global__ __launch_bounds__(256, 2) void mma_av(
    const __half* __restrict__ Af, int lda, size_t sA,
    const __half* __restrict__ Bh, int ldb, size_t sB,
    float* __restrict__ out, int ldc, size_t sC)
{
    extern __shared__ char smem[];
    const uint32_t sbase = smem_u32(smem);
    const int tid = threadIdx.x;
    const int lane = tid & 31, w = tid >> 5;
    const int wm = w & 1, wn = w >> 1;
    const int row0 = blockIdx.y * 128, col0 = blockIdx.x * 128, bz = blockIdx.z;

    const bf16* gA  = (const bf16*)(Af + (size_t)bz * sA + (size_t)row0 * lda);
    const bf16* gBh = (const bf16*)(Bh + (size_t)bz * sB + (size_t)col0 * ldb);

    const int ra  = wm * 64 + (lane & 15);
    const int ca  = lane >> 4;
    const int rsa = ra & 7;
    const int rb  = wn * 32 + (lane & 7) + ((lane >> 4) & 1) * 8;
    const int cb  = (lane >> 3) & 1;
    const int rsb = rb & 7;

    float acc[4][4][4];
#pragma unroll
    for (int i = 0; i < 4; i++)
#pragma unroll
        for (int j = 0; j < 4; j++)
#pragma unroll
            for (int q = 0; q < 4; q++) acc[i][j][q] = 0.f;

    auto issue = [&](int s, int kt) {
        const size_t ko = (size_t)kt * 64;
        const uint32_t sb = sbase + s * STAGE_AV;
        load_tile(gA  + ko, lda, sb,         tid);
        load_tile(gBh + ko, ldb, sb + 16384, tid);
        CP_COMMIT();
    };

    issue(0, 0);
    issue(1, 1);

    for (int kt = 0; kt < KITERS; kt++) {
        if (kt + 1 < KITERS) asm volatile("cp.async.wait_group 1;" ::: "memory");
        else                 asm volatile("cp.async.wait_group 0;" ::: "memory");
        __syncthreads();
        if (kt + 2 < KITERS) issue((kt + 2) % 3, kt + 2);
        const uint32_t sb = sbase + (kt % 3) * STAGE_AV;
        const uint32_t aB = sb, bHb = sb + 16384;

#pragma unroll
        for (int ks = 0; ks < 4; ks++) {
            uint32_t ah[4][4], bh[2][4];
#pragma unroll
            for (int i = 0; i < 4; i++) {
                uint32_t off = (uint32_t)((ra + i * 16) * 128 +
                               ((((ks << 1) | ca) ^ rsa) << 4));
                LDSM4(ah[i][0], ah[i][1], ah[i][2], ah[i][3], aB + off);
            }
#pragma unroll
            for (int jp = 0; jp < 2; jp++) {
                uint32_t off = (uint32_t)((rb + jp * 16) * 128 +
                               ((((ks << 1) | cb) ^ rsb) << 4));
                LDSM4(bh[jp][0], bh[jp][1], bh[jp][2], bh[jp][3], bHb + off);
            }
#pragma unroll
            for (int i = 0; i < 4; i++)
#pragma unroll
                for (int j = 0; j < 4; j++)
                    mma16816h(acc[i][j], ah[i], &bh[j >> 1][(j & 1) << 1]);
        }
    }

#pragma unroll
    for (int j = 0; j < 4; j++) {
        const int cbj = col0 + wn * 32 + j * 8 + ((lane & 3) << 1);
#pragma unroll
        for (int i = 0; i < 4; i++)
#pragma unroll
            for (int rep = 0; rep < 2; rep++) {
                const int rg = row0 + wm * 64 + i * 16 + (lane >> 2) + rep * 8;
                float2* p = (float2*)(out + (size_t)bz * sC + (size_t)rg * ldc + cbj);
                *p = make_float2(acc[i][j][rep * 2 + 0], acc[i][j][rep * 2 + 1]);
            }
    }
}

// ============================================================================
// prep kernels
// ============================================================================
__global__ __launch_bounds__(256) void k_split(const float* __restrict__ s,
                                               bf16* __restrict__ h,
                                               bf16* __restrict__ l, size_t n) {
    size_t i = ((size_t)blockIdx.x * 256 + threadIdx.x) * 4;
    if (i >= n) return;
    float4 v = *reinterpret_cast<const float4*>(s + i);
    bf16 h0, l0, h1, l1, h2, l2, h3, l3;
    split1(v.x, h0, l0); split1(v.y, h1, l1);
    split1(v.z, h2, l2); split1(v.w, h3, l3);
    *reinterpret_cast<uint2*>(h + i) = make_uint2(pack2(h0, h1), pack2(h2, h3));
    *reinterpret_cast<uint2*>(l + i) = make_uint2(pack2(l0, l1), pack2(l2, l3));
}

// z=0: We1 -> W13 bf16 (nOff 0)   z=1: Wk1 -> W13 bf16 (nOff H_)
// z=2: We2 -> We2f fp16 split     z=3: Wk2 -> Wk2T bf16 split
__global__ __launch_bounds__(256) void k_splitT_all(
    const float* __restrict__ We1, const float* __restrict__ Wk1,
    const float* __restrict__ We2, const float* __restrict__ Wk2,
    bf16* __restrict__ W13h, bf16* __restrict__ W13l,
    bf16* __restrict__ Wk2Th, bf16* __restrict__ Wk2Tl,
    __half* __restrict__ We2fh, __half* __restrict__ We2fl)
{
    const int z = blockIdx.z;
    const float* W; int K, Nc, nOff;
    if (z == 0)      { W = We1; K = DIN; Nc = H_;       nOff = 0; }
    else if (z == 1) { W = Wk1; K = DIN; Nc = H_;       nOff = H_; }
    else if (z == 2) { W = We2; K = H_;  Nc = DEMB;     nOff = 0; }
    else             { W = Wk2; K = H_;  Nc = 2 * DATT; nOff = 0; }
    const int k0 = blockIdx.x * 32, n0 = blockIdx.y * 32;
    if (k0 >= K || n0 >= Nc) return;

    __shared__ float t[32][33];
    const int c = threadIdx.x & 31, r = threadIdx.x >> 5;
#pragma unroll
    for (int i = 0; i < 4; i++)
        t[i * 8 + r][c] = W[(size_t)(k0 + i * 8 + r) * Nc + n0 + c];
    __syncthreads();
#pragma unroll
    for (int i = 0; i < 4; i++) {
        const int n = n0 + i * 8 + r;
        const float v = t[c][i * 8 + r];
        if (z <= 1) {
            bf16 h, l; split1(v, h, l);
            W13h[(size_t)(nOff + n) * K + k0 + c] = h;
            W13l[(size_t)(nOff + n) * K + k0 + c] = l;
        } else if (z == 2) {
            __half h, l; split1h(v, h, l);
            We2fh[(size_t)n * K + k0 + c] = h;
            We2fl[(size_t)n * K + k0 + c] = l;
        } else {
            bf16 h, l; split1(v, h, l);
            Wk2Th[(size_t)n * K + k0 + c] = h;
            Wk2Tl[(size_t)n * K + k0 + c] = l;
        }
    }
}

__global__ void k_bias13(const float* __restrict__ be1, const float* __restrict__ bk1,
                         float* __restrict__ b13) {
    int i = blockIdx.x * 256 + threadIdx.x;
    if (i < H_)          b13[i] = be1[i];
    else if (i < 2 * H_) b13[i] = bk1[i - H_];
}

// ============================================================================
// softmax over rows of scores (fp32), output single fp16
// ============================================================================
__global__ __launch_bounds__(256) void k_softmax(const float* __restrict__ S,
                                                 __half* __restrict__ Af) {
    const size_t row = blockIdx.x;
    const float4* r = reinterpret_cast<const float4*>(S + row * N_);
    const int tid = threadIdx.x;
    __shared__ float red[256];

    float4 a = r[tid], b = r[tid + 256];
    float m = fmaxf(fmaxf(fmaxf(a.x, a.y), fmaxf(a.z, a.w)),
                    fmaxf(fmaxf(b.x, b.y), fmaxf(b.z, b.w)));
    red[tid] = m; __syncthreads();
#pragma unroll
    for (int s = 128; s > 0; s >>= 1) {
        if (tid < s) red[tid] = fmaxf(red[tid], red[tid + s]);
        __syncthreads();
    }
    m = red[0]; __syncthreads();

    a.x = __expf(a.x - m); a.y = __expf(a.y - m);
    a.z = __expf(a.z - m); a.w = __expf(a.w - m);
    b.x = __expf(b.x - m); b.y = __expf(b.y - m);
    b.z = __expf(b.z - m); b.w = __expf(b.w - m);
    red[tid] = (a.x + a.y + a.z + a.w) + (b.x + b.y + b.z + b.w);
    __syncthreads();
#pragma unroll
    for (int s = 128; s > 0; s >>= 1) {
        if (tid < s) red[tid] += red[tid + s];
        __syncthreads();
    }
    const float inv = 1.f / red[0];

    uint32_t q0 = pack2h(__float2half_rn(a.x * inv), __float2half_rn(a.y * inv));
    uint32_t q1 = pack2h(__float2half_rn(a.z * inv), __float2half_rn(a.w * inv));
    uint32_t q2 = pack2h(__float2half_rn(b.x * inv), __float2half_rn(b.y * inv));
    uint32_t q3 = pack2h(__float2half_rn(b.z * inv), __float2half_rn(b.w * inv));
    uint2* o = reinterpret_cast<uint2*>(Af + row * N_);
    o[tid]       = make_uint2(q0, q1);
    o[tid + 256] = make_uint2(q2, q3);
}

// ============================================================================
extern "C" void kernel_launch(void* const* d_in, const int* in_sizes, int n_in,
                              void* d_out, int out_size)
{
    const float* x   = (const float*)d_in[0];
    const float* We1 = (const float*)d_in[1];
    const float* be1 = (const float*)d_in[2];
    const float* We2 = (const float*)d_in[3];
    const float* be2 = (const float*)d_in[4];
    const float* Wk1 = (const float*)d_in[5];
    const float* bk1 = (const float*)d_in[6];
    const float* Wk2 = (const float*)d_in[7];
    const float* bk2 = (const float*)d_in[8];
    float* out = (float*)d_out;

    bf16 *xh, *xl, *W13Th, *W13Tl, *Wk2Th, *Wk2Tl, *hh, *hl, *kqh, *kql;
    __half *We2fh, *We2fl, *hf, *eTh, *Af;
    float *scores, *b13;
    cudaGetSymbolAddress((void**)&xh, g_xh);       cudaGetSymbolAddress((void**)&xl, g_xl);
    cudaGetSymbolAddress((void**)&W13Th, g_W13Th); cudaGetSymbolAddress((void**)&W13Tl, g_W13Tl);
    cudaGetSymbolAddress((void**)&Wk2Th, g_Wk2Th); cudaGetSymbolAddress((void**)&Wk2Tl, g_Wk2Tl);
    cudaGetSymbolAddress((void**)&We2fh, g_We2fh); cudaGetSymbolAddress((void**)&We2fl, g_We2fl);
    cudaGetSymbolAddress((void**)&b13, g_b13);
    cudaGetSymbolAddress((void**)&hh, g_hh);       cudaGetSymbolAddress((void**)&hl, g_hl);
    cudaGetSymbolAddress((void**)&hf, g_hf);
    cudaGetSymbolAddress((void**)&eTh, g_eTh);
    cudaGetSymbolAddress((void**)&kqh, g_kqh);     cudaGetSymbolAddress((void**)&kql, g_kql);
    cudaGetSymbolAddress((void**)&scores, g_scores);
    cudaGetSymbolAddress((void**)&Af, g_Af);

    cudaFuncSetAttribute(mma_gemm<8,  true,  true,  4>, cudaFuncAttributeMaxDynamicSharedMemorySize, SMEM_SZ);
    cudaFuncSetAttribute(mma_gemm<16, false, true,  0>, cudaFuncAttributeMaxDynamicSharedMemorySize, SMEM_SZ);
    cudaFuncSetAttribute(mma_gemm<4,  false, false, 2>, cudaFuncAttributeMaxDynamicSharedMemorySize, SMEM_SZ);
    cudaFuncSetAttribute(mma_embs<16>, cudaFuncAttributeMaxDynamicSharedMemorySize, SMEM_EM);
    cudaFuncSetAttribute(mma_av<32>, cudaFuncAttributeMaxDynamicSharedMemorySize, SMEM_AV);

    // ---- prep ----------------------------------------------------------------
    k_split<<<(M_ * DIN / 4 + 255) / 256, 256>>>(x, xh, xl, (size_t)M_ * DIN);
    k_splitT_all<<<dim3(32, 32, 4), 256>>>(We1, Wk1, We2, Wk2,
                                           W13Th, W13Tl, Wk2Th, Wk2Tl, We2fh, We2fl);
    k_bias13<<<(2 * H_ + 255) / 256, 256>>>(be1, bk1, b13);

    // ---- 1) h_all = relu(x @ [We1|Wk1] + [be1|bk1]); also h_f (cols < H_) ----
    mma_gemm<8, true, true, 4><<<dim3((2 * H_) / 128, M_ / 128, 1), 256, SMEM_SZ>>>(
        xh, xl, DIN, 0, W13Th, W13Tl, DIN, 0, b13,
        hh, hl, 2 * H_, 0, hf);

    // ---- 2) kq = h_k @ Wk2 + bk2  (bf16 3-term) -------------------------------
    mma_gemm<16, false, true, 0><<<dim3((2 * DATT) / 128, M_ / 128, 1), 256, SMEM_SZ>>>(
        hh + H_, hl + H_, 2 * H_, 0, Wk2Th, Wk2Tl, H_, 0, bk2,
        kqh, kql, 2 * DATT, 0, nullptr);

    // ---- 3) embsT = (h_f @ We2 + be2)^T  (fp16 2-term, occ 2) -----------------
    mma_embs<16><<<dim3(DEMB / 128, M_ / 128, 1), 256, SMEM_EM>>>(
        hf, H_, We2fh, We2fl, H_, be2, eTh);

    // ---- 4) scores_b = Q_b @ K_b^T  (bf16 3-term, R13) ------------------------
    mma_gemm<4, false, false, 2><<<dim3(N_ / 128, N_ / 128, B_), 256, SMEM_SZ>>>(
        kqh + DATT, kql + DATT, 2 * DATT, (size_t)N_ * 2 * DATT,
        kqh,        kql,        2 * DATT, (size_t)N_ * 2 * DATT,
        nullptr, scores, nullptr, N_, (size_t)N_ * N_, nullptr);

    // ---- 5) softmax -> single fp16 A ------------------------------------------
    k_softmax<<<B_ * N_, 256>>>(scores, Af);

    // ---- 6) out_b = A_b @ embs_b  (fp16 1-term, 2 CTAs/SM) --------------------
    mma_av<32><<<dim3(DEMB / 128, N_ / 128, B_), 256, SMEM_AV>>>(
        Af, N_, (size_t)N_ * N_,
        eTh, N_, (size_t)DEMB * N_,
        out, DEMB, (size_t)N_ * DEMB);
}

// round 16
// speedup vs baseline: 1.1683x; 1.0807x over previous
#include <cuda_runtime.h>
#include <cuda_bf16.h>
#include <cuda_fp16.h>
#include <math.h>
#include <stdint.h>

// ============================================================================
// SimpleAttn via mma.sync. Round 16:
//  - h_k = relu(x @ Wk1 + bk1): bf16 3-term, occ 1 (logit path, full precision)
//  - h_f = relu(x_f @ We1_f + be1): fp16 2-term, occ 2   <-- split from GEMM1
//  - kq  = h_k @ Wk2: bf16 3-term;  embs = h_f @ We2_f: fp16 2-term, occ 2
//  - scores: bf16 3-term;  AV: fp16 1-term, occ 2
// B=8, N=2048, D_IN=512, H=1024, D_EMB=512, D_ATTN=256
// ============================================================================

#define B_   8
#define N_   2048
#define DIN  512
#define H_   1024
#define DEMB 512
#define DATT 256
#define M_   (B_ * N_)   // 16384

typedef __nv_bfloat16 bf16;

// ------------------------- device scratch (no allocs) ----------------------
__device__ __align__(16) bf16 g_xh[(size_t)M_ * DIN],          g_xl[(size_t)M_ * DIN];
__device__ __align__(16) __half g_xfh[(size_t)M_ * DIN],       g_xfl[(size_t)M_ * DIN];
__device__ __align__(16) bf16 g_Wk1Th[(size_t)H_ * DIN],       g_Wk1Tl[(size_t)H_ * DIN];
__device__ __align__(16) __half g_We1f[(size_t)H_ * DIN];
__device__ __align__(16) bf16 g_Wk2Th[(size_t)(2*DATT) * H_],  g_Wk2Tl[(size_t)(2*DATT) * H_];
__device__ __align__(16) __half g_We2fh[(size_t)DEMB * H_],    g_We2fl[(size_t)DEMB * H_];
__device__ __align__(16) bf16 g_hh[(size_t)M_ * H_],           g_hl[(size_t)M_ * H_];
__device__ __align__(16) __half g_hf[(size_t)M_ * H_];
__device__ __align__(16) __half g_eTh[(size_t)B_ * DEMB * N_];
__device__ __align__(16) bf16 g_kqh[(size_t)M_ * (2*DATT)],    g_kql[(size_t)M_ * (2*DATT)];
__device__ __align__(16) float g_scores[(size_t)B_ * N_ * N_];
__device__ __align__(16) __half g_Af[(size_t)B_ * N_ * N_];

// ------------------------- helpers -----------------------------------------
__device__ __forceinline__ uint32_t smem_u32(const void* p) {
    uint32_t a;
    asm("{ .reg .u64 t; cvta.to.shared.u64 t, %1; cvt.u32.u64 %0, t; }"
        : "=r"(a) : "l"(p));
    return a;
}

__device__ __forceinline__ uint32_t pack2(bf16 a, bf16 b) {
    return (uint32_t)__bfloat16_as_ushort(a) | ((uint32_t)__bfloat16_as_ushort(b) << 16);
}
__device__ __forceinline__ uint32_t pack2h(__half a, __half b) {
    return (uint32_t)__half_as_ushort(a) | ((uint32_t)__half_as_ushort(b) << 16);
}
__device__ __forceinline__ void split1(float v, bf16& h, bf16& l) {
    h = __float2bfloat16(v);
    l = __float2bfloat16(v - __bfloat162float(h));
}
__device__ __forceinline__ void split1h(float v, __half& h, __half& l) {
    h = __float2half_rn(v);
    l = __float2half_rn(v - __half2float(h));
}

#define LDSM4(r0, r1, r2, r3, addr) \
    asm volatile("ldmatrix.sync.aligned.m8n8.x4.shared.b16 {%0,%1,%2,%3}, [%4];" \
        : "=r"(r0), "=r"(r1), "=r"(r2), "=r"(r3) : "r"(addr))

__device__ __forceinline__ void mma16816(float* d, const uint32_t* a, const uint32_t* b) {
    asm volatile(
        "mma.sync.aligned.m16n8k16.row.col.f32.bf16.bf16.f32 "
        "{%0,%1,%2,%3}, {%4,%5,%6,%7}, {%8,%9}, {%0,%1,%2,%3};"
        : "+f"(d[0]), "+f"(d[1]), "+f"(d[2]), "+f"(d[3])
        : "r"(a[0]), "r"(a[1]), "r"(a[2]), "r"(a[3]), "r"(b[0]), "r"(b[1]));
}
__device__ __forceinline__ void mma16816h(float* d, const uint32_t* a, const uint32_t* b) {
    asm volatile(
        "mma.sync.aligned.m16n8k16.row.col.f32.f16.f16.f32 "
        "{%0,%1,%2,%3}, {%4,%5,%6,%7}, {%8,%9}, {%0,%1,%2,%3};"
        : "+f"(d[0]), "+f"(d[1]), "+f"(d[2]), "+f"(d[3])
        : "r"(a[0]), "r"(a[1]), "r"(a[2]), "r"(a[3]), "r"(b[0]), "r"(b[1]));
}

#define CP_ASYNC16(dst, src) \
    asm volatile("cp.async.cg.shared.global [%0], [%1], 16;" :: "r"(dst), "l"(src))
#define CP_COMMIT() asm volatile("cp.async.commit_group;" ::: "memory")

// tile loader: 128 rows x 64 x 2B, XOR swizzle (chunk c of row r at c ^ (r&7))
__device__ __forceinline__ void load_tile(const bf16* __restrict__ g, int ld,
                                          uint32_t sm, int tid) {
#pragma unroll
    for (int i = 0; i < 4; i++) {
        int idx = i * 256 + tid;
        int r = idx >> 3;
        int c = idx & 7;
        const bf16* src = g + (size_t)r * ld + c * 8;
        uint32_t dst = sm + (uint32_t)(r * 128 + ((c ^ (r & 7)) << 4));
        CP_ASYNC16(dst, src);
    }
}

#define STAGE_SZ 65536              // 4 tiles x 16KB
#define SMEM_SZ  (3 * STAGE_SZ)     // 196608, 1 CTA/SM
#define STAGE_AV 32768              // 2 tiles
#define SMEM_AV  (3 * STAGE_AV)     // 98304, 2 CTAs/SM
#define STAGE_EM 49152              // 3 tiles
#define SMEM_EM  (2 * STAGE_EM)     // 98304, 2 CTAs/SM

// ============================================================================
// Split-bf16 GEMM (3-term), BK=64, 3-stage, acc-major (R9-proven).
// OMODE: 0 = split bf16 row-major;  2 = fp32 row-major (batch stride sC)
// ============================================================================
template <int KITERS, bool RELU, bool HAS_BIAS, int OMODE>
__global__ __launch_bounds__(256, 1) void mma_gemm(
    const bf16* __restrict__ Ah, const bf16* __restrict__ Al, int lda, size_t sA,
    const bf16* __restrict__ Bh, const bf16* __restrict__ Bl, int ldb, size_t sB,
    const float* __restrict__ bias,
    void* outHi, void* outLo, int ldc, size_t sC)
{
    extern __shared__ char smem[];
    const uint32_t sbase = smem_u32(smem);
    const int tid = threadIdx.x;
    const int lane = tid & 31, w = tid >> 5;
    const int wm = w & 1, wn = w >> 1;
    const int row0 = blockIdx.y * 128, col0 = blockIdx.x * 128, bz = blockIdx.z;

    const bf16* gAh = Ah + (size_t)bz * sA + (size_t)row0 * lda;
    const bf16* gAl = Al + (size_t)bz * sA + (size_t)row0 * lda;
    const bf16* gBh = Bh + (size_t)bz * sB + (size_t)col0 * ldb;
    const bf16* gBl = Bl + (size_t)bz * sB + (size_t)col0 * ldb;

    const int ra  = wm * 64 + (lane & 15);
    const int ca  = lane >> 4;
    const int rsa = ra & 7;
    const int rb  = wn * 32 + (lane & 7) + ((lane >> 4) & 1) * 8;
    const int cb  = (lane >> 3) & 1;
    const int rsb = rb & 7;

    float acc[4][4][4];
#pragma unroll
    for (int i = 0; i < 4; i++)
#pragma unroll
        for (int j = 0; j < 4; j++)
#pragma unroll
            for (int q = 0; q < 4; q++) acc[i][j][q] = 0.f;

    auto issue = [&](int s, int kt) {
        const size_t ko = (size_t)kt * 64;
        const uint32_t sb = sbase + s * STAGE_SZ;
        load_tile(gAh + ko, lda, sb,             tid);
        load_tile(gAl + ko, lda, sb + 16384,     tid);
        load_tile(gBh + ko, ldb, sb + 32768,     tid);
        load_tile(gBl + ko, ldb, sb + 49152,     tid);
        CP_COMMIT();
    };

    issue(0, 0);
    issue(1, 1);

    for (int kt = 0; kt < KITERS; kt++) {
        if (kt + 1 < KITERS) asm volatile("cp.async.wait_group 1;" ::: "memory");
        else                 asm volatile("cp.async.wait_group 0;" ::: "memory");
        __syncthreads();
        if (kt + 2 < KITERS) issue((kt + 2) % 3, kt + 2);
        const uint32_t sb  = sbase + (kt % 3) * STAGE_SZ;
        const uint32_t aHb = sb, aLb = sb + 16384, bHb = sb + 32768, bLb = sb + 49152;

#pragma unroll
        for (int ks = 0; ks < 4; ks++) {
            uint32_t ah[4][4], alr[4][4], bh[2][4], blr[2][4];
#pragma unroll
            for (int i = 0; i < 4; i++) {
                uint32_t off = (uint32_t)((ra + i * 16) * 128 +
                               ((((ks << 1) | ca) ^ rsa) << 4));
                LDSM4(ah[i][0],  ah[i][1],  ah[i][2],  ah[i][3],  aHb + off);
                LDSM4(alr[i][0], alr[i][1], alr[i][2], alr[i][3], aLb + off);
            }
#pragma unroll
            for (int jp = 0; jp < 2; jp++) {
                uint32_t off = (uint32_t)((rb + jp * 16) * 128 +
                               ((((ks << 1) | cb) ^ rsb) << 4));
                LDSM4(bh[jp][0],  bh[jp][1],  bh[jp][2],  bh[jp][3],  bHb + off);
                LDSM4(blr[jp][0], blr[jp][1], blr[jp][2], blr[jp][3], bLb + off);
            }
#pragma unroll
            for (int i = 0; i < 4; i++)
#pragma unroll
                for (int j = 0; j < 4; j++) {
                    const uint32_t* bph = &bh[j >> 1][(j & 1) << 1];
                    const uint32_t* bpl = &blr[j >> 1][(j & 1) << 1];
                    mma16816(acc[i][j], ah[i], bph);
                    mma16816(acc[i][j], ah[i], bpl);
                    mma16816(acc[i][j], alr[i], bph);
                }
        }
    }

#pragma unroll
    for (int j = 0; j < 4; j++) {
        const int cbj = col0 + wn * 32 + j * 8 + ((lane & 3) << 1);
        const float bb0 = HAS_BIAS ? bias[cbj] : 0.f;
        const float bb1 = HAS_BIAS ? bias[cbj + 1] : 0.f;
#pragma unroll
        for (int i = 0; i < 4; i++)
#pragma unroll
            for (int rep = 0; rep < 2; rep++) {
                const int rg = row0 + wm * 64 + i * 16 + (lane >> 2) + rep * 8;
                float v0 = acc[i][j][rep * 2 + 0] + bb0;
                float v1 = acc[i][j][rep * 2 + 1] + bb1;
                if (RELU) { v0 = fmaxf(v0, 0.f); v1 = fmaxf(v1, 0.f); }
                if (OMODE == 2) {
                    float2* p = (float2*)((float*)outHi + (size_t)bz * sC +
                                          (size_t)rg * ldc + cbj);
                    *p = make_float2(v0, v1);
                } else {
                    bf16 h0, l0, h1, l1;
                    split1(v0, h0, l0); split1(v1, h1, l1);
                    *(uint32_t*)((bf16*)outHi + (size_t)rg * ldc + cbj) = pack2(h0, h1);
                    *(uint32_t*)((bf16*)outLo + (size_t)rg * ldc + cbj) = pack2(l0, l1);
                }
            }
    }
}

// ============================================================================
// h1 GEMM: h_f = relu(x_f(hi/lo fp16) @ We1_f(single) + be1), 2-term, occ 2,
// row-major fp16 single output.
// ============================================================================
template <int KITERS>
__global__ __launch_bounds__(256, 2) void mma_h1(
    const __half* __restrict__ Afh, const __half* __restrict__ Afl, int lda,
    const __half* __restrict__ Bf, int ldb,
    const float* __restrict__ bias,
    __half* __restrict__ outF, int ldc)
{
    extern __shared__ char smem[];
    const uint32_t sbase = smem_u32(smem);
    const int tid = threadIdx.x;
    const int lane = tid & 31, w = tid >> 5;
    const int wm = w & 1, wn = w >> 1;
    const int row0 = blockIdx.y * 128, col0 = blockIdx.x * 128;

    const bf16* gAh = (const bf16*)(Afh + (size_t)row0 * lda);
    const bf16* gAl = (const bf16*)(Afl + (size_t)row0 * lda);
    const bf16* gB  = (const bf16*)(Bf + (size_t)col0 * ldb);

    const int ra  = wm * 64 + (lane & 15);
    const int ca  = lane >> 4;
    const int rsa = ra & 7;
    const int rb  = wn * 32 + (lane & 7) + ((lane >> 4) & 1) * 8;
    const int cb  = (lane >> 3) & 1;
    const int rsb = rb & 7;

    float acc[4][4][4];
#pragma unroll
    for (int i = 0; i < 4; i++)
#pragma unroll
        for (int j = 0; j < 4; j++)
#pragma unroll
            for (int q = 0; q < 4; q++) acc[i][j][q] = 0.f;

    auto issue = [&](int s, int kt) {
        const size_t ko = (size_t)kt * 64;
        const uint32_t sb = sbase + s * STAGE_EM;
        load_tile(gAh + ko, lda, sb,         tid);
        load_tile(gAl + ko, lda, sb + 16384, tid);
        load_tile(gB  + ko, ldb, sb + 32768, tid);
        CP_COMMIT();
    };

    issue(0, 0);
    issue(1, 1);

    for (int kt = 0; kt < KITERS; kt++) {
        if (kt + 1 < KITERS) asm volatile("cp.async.wait_group 1;" ::: "memory");
        else                 asm volatile("cp.async.wait_group 0;" ::: "memory");
        __syncthreads();
        const uint32_t sb  = sbase + (kt & 1) * STAGE_EM;
        const uint32_t aHb = sb, aLb = sb + 16384, bB = sb + 32768;

#pragma unroll
        for (int ks = 0; ks < 4; ks++) {
            uint32_t ah[4][4], alr[4][4], bf_[2][4];
#pragma unroll
            for (int i = 0; i < 4; i++) {
                uint32_t off = (uint32_t)((ra + i * 16) * 128 +
                               ((((ks << 1) | ca) ^ rsa) << 4));
                LDSM4(ah[i][0],  ah[i][1],  ah[i][2],  ah[i][3],  aHb + off);
                LDSM4(alr[i][0], alr[i][1], alr[i][2], alr[i][3], aLb + off);
            }
#pragma unroll
            for (int jp = 0; jp < 2; jp++) {
                uint32_t off = (uint32_t)((rb + jp * 16) * 128 +
                               ((((ks << 1) | cb) ^ rsb) << 4));
                LDSM4(bf_[jp][0], bf_[jp][1], bf_[jp][2], bf_[jp][3], bB + off);
            }
#pragma unroll
            for (int i = 0; i < 4; i++)
#pragma unroll
                for (int j = 0; j < 4; j++) {
                    const uint32_t* bp = &bf_[j >> 1][(j & 1) << 1];
                    mma16816h(acc[i][j], ah[i],  bp);
                    mma16816h(acc[i][j], alr[i], bp);
                }
        }
        __syncthreads();
        if (kt + 2 < KITERS) issue(kt & 1, kt + 2);
    }

#pragma unroll
    for (int j = 0; j < 4; j++) {
        const int cbj = col0 + wn * 32 + j * 8 + ((lane & 3) << 1);
        const float bb0 = bias[cbj];
        const float bb1 = bias[cbj + 1];
#pragma unroll
        for (int i = 0; i < 4; i++)
#pragma unroll
            for (int rep = 0; rep < 2; rep++) {
                const int rg = row0 + wm * 64 + i * 16 + (lane >> 2) + rep * 8;
                float v0 = fmaxf(acc[i][j][rep * 2 + 0] + bb0, 0.f);
                float v1 = fmaxf(acc[i][j][rep * 2 + 1] + bb1, 0.f);
                *(uint32_t*)(outF + (size_t)rg * ldc + cbj) =
                    pack2h(__float2half_rn(v0), __float2half_rn(v1));
            }
    }
}

// ============================================================================
// embs GEMM: fp16 2-term (A = h_f single, B = We2 fp16 hi/lo), 2-stage,
// 2 CTAs/SM; transposed single-fp16 epilogue into embsT[b][DEMB][N_] + bias.
// ============================================================================
template <int KITERS>
__global__ __launch_bounds__(256, 2) void mma_embs(
    const __half* __restrict__ Af, int lda,
    const __half* __restrict__ Bh, const __half* __restrict__ Bl, int ldb,
    const float* __restrict__ bias,
    __half* __restrict__ outT)
{
    extern __shared__ char smem[];
    const uint32_t sbase = smem_u32(smem);
    const int tid = threadIdx.x;
    const int lane = tid & 31, w = tid >> 5;
    const int wm = w & 1, wn = w >> 1;
    const int row0 = blockIdx.y * 128, col0 = blockIdx.x * 128;

    const bf16* gA  = (const bf16*)(Af + (size_t)row0 * lda);
    const bf16* gBh = (const bf16*)(Bh + (size_t)col0 * ldb);
    const bf16* gBl = (const bf16*)(Bl + (size_t)col0 * ldb);

    const int ra  = wm * 64 + (lane & 15);
    const int ca  = lane >> 4;
    const int rsa = ra & 7;
    const int rb  = wn * 32 + (lane & 7) + ((lane >> 4) & 1) * 8;
    const int cb  = (lane >> 3) & 1;
    const int rsb = rb & 7;

    float acc[4][4][4];
#pragma unroll
    for (int i = 0; i < 4; i++)
#pragma unroll
        for (int j = 0; j < 4; j++)
#pragma unroll
            for (int q = 0; q < 4; q++) acc[i][j][q] = 0.f;

    auto issue = [&](int s, int kt) {
        const size_t ko = (size_t)kt * 64;
        const uint32_t sb = sbase + s * STAGE_EM;
        load_tile(gA  + ko, lda, sb,         tid);
        load_tile(gBh + ko, ldb, sb + 16384, tid);
        load_tile(gBl + ko, ldb, sb + 32768, tid);
        CP_COMMIT();
    };

    issue(0, 0);
    issue(1, 1);

    for (int kt = 0; kt < KITERS; kt++) {
        if (kt + 1 < KITERS) asm volatile("cp.async.wait_group 1;" ::: "memory");
        else                 asm volatile("cp.async.wait_group 0;" ::: "memory");
        __syncthreads();
        const uint32_t sb  = sbase + (kt & 1) * STAGE_EM;
        const uint32_t aB = sb, bHb = sb + 16384, bLb = sb + 32768;

#pragma unroll
        for (int ks = 0; ks < 4; ks++) {
            uint32_t ah[4][4], bh[2][4], blr[2][4];
#pragma unroll
            for (int i = 0; i < 4; i++) {
                uint32_t off = (uint32_t)((ra + i * 16) * 128 +
                               ((((ks << 1) | ca) ^ rsa) << 4));
                LDSM4(ah[i][0], ah[i][1], ah[i][2], ah[i][3], aB + off);
            }
#pragma unroll
            for (int jp = 0; jp < 2; jp++) {
                uint32_t off = (uint32_t)((rb + jp * 16) * 128 +
                               ((((ks << 1) | cb) ^ rsb) << 4));
                LDSM4(bh[jp][0],  bh[jp][1],  bh[jp][2],  bh[jp][3],  bHb + off);
                LDSM4(blr[jp][0], blr[jp][1], blr[jp][2], blr[jp][3], bLb + off);
            }
#pragma unroll
            for (int i = 0; i < 4; i++)
#pragma unroll
                for (int j = 0; j < 4; j++) {
                    mma16816h(acc[i][j], ah[i], &bh[j >> 1][(j & 1) << 1]);
                    mma16816h(acc[i][j], ah[i], &blr[j >> 1][(j & 1) << 1]);
                }
        }
        __syncthreads();
        if (kt + 2 < KITERS) issue(kt & 1, kt + 2);
    }

    // transposed single fp16 write, with bias
    float* buf = reinterpret_cast<float*>(smem) + w * 2112;   // 64 x 33
#pragma unroll
    for (int i = 0; i < 4; i++)
#pragma unroll
        for (int j = 0; j < 4; j++)
#pragma unroll
            for (int rep = 0; rep < 2; rep++) {
                const int ml = i * 16 + (lane >> 2) + rep * 8;
                const int nl = j * 8 + ((lane & 3) << 1);
                buf[ml * 33 + nl]     = acc[i][j][rep * 2 + 0];
                buf[ml * 33 + nl + 1] = acc[i][j][rep * 2 + 1];
            }
    __syncwarp();
    const int colsel = lane >> 3;
    const int seg    = lane & 7;
    const int rowg0 = row0 + wm * 64;
    const int b = rowg0 >> 11, pos = rowg0 & (N_ - 1);
#pragma unroll
    for (int cp = 0; cp < 8; cp++) {
        const int csub = cp * 4 + colsel;
        const int colg = col0 + wn * 32 + csub;
        const float fb = bias[colg];
        uint32_t ph[4];
#pragma unroll
        for (int q = 0; q < 4; q++) {
            float v0 = buf[(seg * 8 + 2 * q) * 33 + csub] + fb;
            float v1 = buf[(seg * 8 + 2 * q + 1) * 33 + csub] + fb;
            ph[q] = pack2h(__float2half_rn(v0), __float2half_rn(v1));
        }
        const size_t addr = ((size_t)b * DEMB + colg) * (size_t)N_ + pos + seg * 8;
        *(uint4*)(outT + addr) = make_uint4(ph[0], ph[1], ph[2], ph[3]);
    }
}

// ============================================================================
// AV GEMM, fp16 1-term, 3-stage, 2 CTAs/SM (exactly R13).
// ============================================================================
template <int KITERS>
__global__ __launch_bounds__(256, 2) void mma_av(
    const __half* __restrict__ Af, int lda, size_t sA,
    const __half* __restrict__ Bh, int ldb, size_t sB,
    float* __restrict__ out, int ldc, size_t sC)
{
    extern __shared__ char smem[];
    const uint32_t sbase = smem_u32(smem);
    const int tid = threadIdx.x;
    const int lane = tid & 31, w = tid >> 5;
    const int wm = w & 1, wn = w >> 1;
    const int row0 = blockIdx.y * 128, col0 = blockIdx.x * 128, bz = blockIdx.z;

    const bf16* gA  = (const bf16*)(Af + (size_t)bz * sA + (size_t)row0 * lda);
    const bf16* gBh = (const bf16*)(Bh + (size_t)bz * sB + (size_t)col0 * ldb);

    const int ra  = wm * 64 + (lane & 15);
    const int ca  = lane >> 4;
    const int rsa = ra & 7;
    const int rb  = wn * 32 + (lane & 7) + ((lane >> 4) & 1) * 8;
    const int cb  = (lane >> 3) & 1;
    const int rsb = rb & 7;

    float acc[4][4][4];
#pragma unroll
    for (int i = 0; i < 4; i++)
#pragma unroll
        for (int j = 0; j < 4; j++)
#pragma unroll
            for (int q = 0; q < 4; q++) acc[i][j][q] = 0.f;

    auto issue = [&](int s, int kt) {
        const size_t ko = (size_t)kt * 64;
        const uint32_t sb = sbase + s * STAGE_AV;
        load_tile(gA  + ko, lda, sb,         tid);
        load_tile(gBh + ko, ldb, sb + 16384, tid);
        CP_COMMIT();
    };

    issue(0, 0);
    issue(1, 1);

    for (int kt = 0; kt < KITERS; kt++) {
        if (kt + 1 < KITERS) asm volatile("cp.async.wait_group 1;" ::: "memory");
        else                 asm volatile("cp.async.wait_group 0;" ::: "memory");
        __syncthreads();
        if (kt + 2 < KITERS) issue((kt + 2) % 3, kt + 2);
        const uint32_t sb = sbase + (kt % 3) * STAGE_AV;
        const uint32_t aB = sb, bHb = sb + 16384;

#pragma unroll
        for (int ks = 0; ks < 4; ks++) {
            uint32_t ah[4][4], bh[2][4];
#pragma unroll
            for (int i = 0; i < 4; i++) {
                uint32_t off = (uint32_t)((ra + i * 16) * 128 +
                               ((((ks << 1) | ca) ^ rsa) << 4));
                LDSM4(ah[i][0], ah[i][1], ah[i][2], ah[i][3], aB + off);
            }
#pragma unroll
            for (int jp = 0; jp < 2; jp++) {
                uint32_t off = (uint32_t)((rb + jp * 16) * 128 +
                               ((((ks << 1) | cb) ^ rsb) << 4));
                LDSM4(bh[jp][0], bh[jp][1], bh[jp][2], bh[jp][3], bHb + off);
            }
#pragma unroll
            for (int i = 0; i < 4; i++)
#pragma unroll
                for (int j = 0; j < 4; j++)
                    mma16816h(acc[i][j], ah[i], &bh[j >> 1][(j & 1) << 1]);
        }
    }

#pragma unroll
    for (int j = 0; j < 4; j++) {
        const int cbj = col0 + wn * 32 + j * 8 + ((lane & 3) << 1);
#pragma unroll
        for (int i = 0; i < 4; i++)
#pragma unroll
            for (int rep = 0; rep < 2; rep++) {
                const int rg = row0 + wm * 64 + i * 16 + (lane >> 2) + rep * 8;
                float2* p = (float2*)(out + (size_t)bz * sC + (size_t)rg * ldc + cbj);
                *p = make_float2(acc[i][j][rep * 2 + 0], acc[i][j][rep * 2 + 1]);
            }
    }
}

// ============================================================================
// prep kernels
// ============================================================================
// x -> bf16 hi/lo (for kq path) AND fp16 hi/lo (for embs path)
__global__ __launch_bounds__(256) void k_split(const float* __restrict__ s,
                                               bf16* __restrict__ h,
                                               bf16* __restrict__ l,
                                               __half* __restrict__ fh,
                                               __half* __restrict__ fl, size_t n) {
    size_t i = ((size_t)blockIdx.x * 256 + threadIdx.x) * 4;
    if (i >= n) return;
    float4 v = *reinterpret_cast<const float4*>(s + i);
    bf16 h0, l0, h1, l1, h2, l2, h3, l3;
    split1(v.x, h0, l0); split1(v.y, h1, l1);
    split1(v.z, h2, l2); split1(v.w, h3, l3);
    *reinterpret_cast<uint2*>(h + i) = make_uint2(pack2(h0, h1), pack2(h2, h3));
    *reinterpret_cast<uint2*>(l + i) = make_uint2(pack2(l0, l1), pack2(l2, l3));
    __half fh0, fl0, fh1, fl1, fh2, fl2, fh3, fl3;
    split1h(v.x, fh0, fl0); split1h(v.y, fh1, fl1);
    split1h(v.z, fh2, fl2); split1h(v.w, fh3, fl3);
    *reinterpret_cast<uint2*>(fh + i) = make_uint2(pack2h(fh0, fh1), pack2h(fh2, fh3));
    *reinterpret_cast<uint2*>(fl + i) = make_uint2(pack2h(fl0, fl1), pack2h(fl2, fl3));
}

// z=0: We1 -> We1f fp16 single; z=1: Wk1 -> Wk1T bf16 split
// z=2: We2 -> We2f fp16 split;  z=3: Wk2 -> Wk2T bf16 split
__global__ __launch_bounds__(256) void k_splitT_all(
    const float* __restrict__ We1, const float* __restrict__ Wk1,
    const float* __restrict__ We2, const float* __restrict__ Wk2,
    __half* __restrict__ We1f,
    bf16* __restrict__ Wk1Th, bf16* __restrict__ Wk1Tl,
    __half* __restrict__ We2fh, __half* __restrict__ We2fl,
    bf16* __restrict__ Wk2Th, bf16* __restrict__ Wk2Tl)
{
    const int z = blockIdx.z;
    const float* W; int K, Nc;
    if (z == 0)      { W = We1; K = DIN; Nc = H_; }
    else if (z == 1) { W = Wk1; K = DIN; Nc = H_; }
    else if (z == 2) { W = We2; K = H_;  Nc = DEMB; }
    else             { W = Wk2; K = H_;  Nc = 2 * DATT; }
    const int k0 = blockIdx.x * 32, n0 = blockIdx.y * 32;
    if (k0 >= K || n0 >= Nc) return;

    __shared__ float t[32][33];
    const int c = threadIdx.x & 31, r = threadIdx.x >> 5;
#pragma unroll
    for (int i = 0; i < 4; i++)
        t[i * 8 + r][c] = W[(size_t)(k0 + i * 8 + r) * Nc + n0 + c];
    __syncthreads();
#pragma unroll
    for (int i = 0; i < 4; i++) {
        const int n = n0 + i * 8 + r;
        const float v = t[c][i * 8 + r];
        const size_t idx = (size_t)n * K + k0 + c;
        if (z == 0) {
            We1f[idx] = __float2half_rn(v);
        } else if (z == 1) {
            bf16 h, l; split1(v, h, l);
            Wk1Th[idx] = h; Wk1Tl[idx] = l;
        } else if (z == 2) {
            __half h, l; split1h(v, h, l);
            We2fh[idx] = h; We2fl[idx] = l;
        } else {
            bf16 h, l; split1(v, h, l);
            Wk2Th[idx] = h; Wk2Tl[idx] = l;
        }
    }
}

// ============================================================================
// softmax over rows of scores (fp32), output single fp16
// ============================================================================
__global__ __launch_bounds__(256) void k_softmax(const float* __restrict__ S,
                                                 __half* __restrict__ Af) {
    const size_t row = blockIdx.x;
    const float4* r = reinterpret_cast<const float4*>(S + row * N_);
    const int tid = threadIdx.x;
    __shared__ float red[256];

    float4 a = r[tid], b = r[tid + 256];
    float m = fmaxf(fmaxf(fmaxf(a.x, a.y), fmaxf(a.z, a.w)),
                    fmaxf(fmaxf(b.x, b.y), fmaxf(b.z, b.w)));
    red[tid] = m; __syncthreads();
#pragma unroll
    for (int s = 128; s > 0; s >>= 1) {
        if (tid < s) red[tid] = fmaxf(red[tid], red[tid + s]);
        __syncthreads();
    }
    m = red[0]; __syncthreads();

    a.x = __expf(a.x - m); a.y = __expf(a.y - m);
    a.z = __expf(a.z - m); a.w = __expf(a.w - m);
    b.x = __expf(b.x - m); b.y = __expf(b.y - m);
    b.z = __expf(b.z - m); b.w = __expf(b.w - m);
    red[tid] = (a.x + a.y + a.z + a.w) + (b.x + b.y + b.z + b.w);
    __syncthreads();
#pragma unroll
    for (int s = 128; s > 0; s >>= 1) {
        if (tid < s) red[tid] += red[tid + s];
        __syncthreads();
    }
    const float inv = 1.f / red[0];

    uint32_t q0 = pack2h(__float2half_rn(a.x * inv), __float2half_rn(a.y * inv));
    uint32_t q1 = pack2h(__float2half_rn(a.z * inv), __float2half_rn(a.w * inv));
    uint32_t q2 = pack2h(__float2half_rn(b.x * inv), __float2half_rn(b.y * inv));
    uint32_t q3 = pack2h(__float2half_rn(b.z * inv), __float2half_rn(b.w * inv));
    uint2* o = reinterpret_cast<uint2*>(Af + row * N_);
    o[tid]       = make_uint2(q0, q1);
    o[tid + 256] = make_uint2(q2, q3);
}

// ============================================================================
extern "C" void kernel_launch(void* const* d_in, const int* in_sizes, int n_in,
                              void* d_out, int out_size)
{
    const float* x   = (const float*)d_in[0];
    const float* We1 = (const float*)d_in[1];
    const float* be1 = (const float*)d_in[2];
    const float* We2 = (const float*)d_in[3];
    const float* be2 = (const float*)d_in[4];
    const float* Wk1 = (const float*)d_in[5];
    const float* bk1 = (const float*)d_in[6];
    const float* Wk2 = (const float*)d_in[7];
    const float* bk2 = (const float*)d_in[8];
    float* out = (float*)d_out;

    bf16 *xh, *xl, *Wk1Th, *Wk1Tl, *Wk2Th, *Wk2Tl, *hh, *hl, *kqh, *kql;
    __half *xfh, *xfl, *We1f, *We2fh, *We2fl, *hf, *eTh, *Af;
    float *scores;
    cudaGetSymbolAddress((void**)&xh, g_xh);       cudaGetSymbolAddress((void**)&xl, g_xl);
    cudaGetSymbolAddress((void**)&xfh, g_xfh);     cudaGetSymbolAddress((void**)&xfl, g_xfl);
    cudaGetSymbolAddress((void**)&Wk1Th, g_Wk1Th); cudaGetSymbolAddress((void**)&Wk1Tl, g_Wk1Tl);
    cudaGetSymbolAddress((void**)&We1f, g_We1f);
    cudaGetSymbolAddress((void**)&Wk2Th, g_Wk2Th); cudaGetSymbolAddress((void**)&Wk2Tl, g_Wk2Tl);
    cudaGetSymbolAddress((void**)&We2fh, g_We2fh); cudaGetSymbolAddress((void**)&We2fl, g_We2fl);
    cudaGetSymbolAddress((void**)&hh, g_hh);       cudaGetSymbolAddress((void**)&hl, g_hl);
    cudaGetSymbolAddress((void**)&hf, g_hf);
    cudaGetSymbolAddress((void**)&eTh, g_eTh);
    cudaGetSymbolAddress((void**)&kqh, g_kqh);     cudaGetSymbolAddress((void**)&kql, g_kql);
    cudaGetSymbolAddress((void**)&scores, g_scores);
    cudaGetSymbolAddress((void**)&Af, g_Af);

    cudaFuncSetAttribute(mma_gemm<8,  true,  true,  0>, cudaFuncAttributeMaxDynamicSharedMemorySize, SMEM_SZ);
    cudaFuncSetAttribute(mma_gemm<16, false, true,  0>, cudaFuncAttributeMaxDynamicSharedMemorySize, SMEM_SZ);
    cudaFuncSetAttribute(mma_gemm<4,  false, false, 2>, cudaFuncAttributeMaxDynamicSharedMemorySize, SMEM_SZ);
    cudaFuncSetAttribute(mma_h1<8>,   cudaFuncAttributeMaxDynamicSharedMemorySize, SMEM_EM);
    cudaFuncSetAttribute(mma_embs<16>, cudaFuncAttributeMaxDynamicSharedMemorySize, SMEM_EM);
    cudaFuncSetAttribute(mma_av<32>,  cudaFuncAttributeMaxDynamicSharedMemorySize, SMEM_AV);

    // ---- prep ----------------------------------------------------------------
    k_split<<<(M_ * DIN / 4 + 255) / 256, 256>>>(x, xh, xl, xfh, xfl, (size_t)M_ * DIN);
    k_splitT_all<<<dim3(32, 32, 4), 256>>>(We1, Wk1, We2, Wk2,
                                           We1f, Wk1Th, Wk1Tl, We2fh, We2fl,
                                           Wk2Th, Wk2Tl);

    // ---- 1) h_k = relu(x @ Wk1 + bk1)  (bf16 3-term, N=1024) ------------------
    mma_gemm<8, true, true, 0><<<dim3(H_ / 128, M_ / 128, 1), 256, SMEM_SZ>>>(
        xh, xl, DIN, 0, Wk1Th, Wk1Tl, DIN, 0, bk1,
        hh, hl, H_, 0);

    // ---- 2) h_f = relu(x_f @ We1_f + be1)  (fp16 2-term, occ 2) ---------------
    mma_h1<8><<<dim3(H_ / 128, M_ / 128, 1), 256, SMEM_EM>>>(
        xfh, xfl, DIN, We1f, DIN, be1, hf, H_);

    // ---- 3) kq = h_k @ Wk2 + bk2  (bf16 3-term) -------------------------------
    mma_gemm<16, false, true, 0><<<dim3((2 * DATT) / 128, M_ / 128, 1), 256, SMEM_SZ>>>(
        hh, hl, H_, 0, Wk2Th, Wk2Tl, H_, 0, bk2,
        kqh, kql, 2 * DATT, 0);

    // ---- 4) embsT = (h_f @ We2_f + be2)^T  (fp16 2-term, occ 2) ---------------
    mma_embs<16><<<dim3(DEMB / 128, M_ / 128, 1), 256, SMEM_EM>>>(
        hf, H_, We2fh, We2fl, H_, be2, eTh);

    // ---- 5) scores_b = Q_b @ K_b^T  (bf16 3-term) -----------------------------
    mma_gemm<4, false, false, 2><<<dim3(N_ / 128, N_ / 128, B_), 256, SMEM_SZ>>>(
        kqh + DATT, kql + DATT, 2 * DATT, (size_t)N_ * 2 * DATT,
        kqh,        kql,        2 * DATT, (size_t)N_ * 2 * DATT,
        nullptr, scores, nullptr, N_, (size_t)N_ * N_);

    // ---- 6) softmax -> single fp16 A ------------------------------------------
    k_softmax<<<B_ * N_, 256>>>(scores, Af);

    // ---- 7) out_b = A_b @ embs_b  (fp16 1-term, 2 CTAs/SM) --------------------
    mma_av<32><<<dim3(DEMB / 128, N_ / 128, B_), 256, SMEM_AV>>>(
        Af, N_, (size_t)N_ * N_,
        eTh, N_, (size_t)DEMB * N_,
        out, DEMB, (size_t)N_ * DEMB);
}

// round 17
// speedup vs baseline: 1.3094x; 1.1208x over previous
#include <cuda_runtime.h>
#include <cuda_bf16.h>
#include <cuda_fp16.h>
#include <math.h>
#include <stdint.h>

// ============================================================================
// SimpleAttn via mma.sync. Round 17:
//  - logit path (h_k, kq, scores): bf16 3-term, occ 1 (irreducible precision)
//  - h1:   x_f(single) @ We1_f(single), fp16 1-term, 3-stage, occ 2   <-- new
//  - embs: h_f @ We2_f(single),         fp16 1-term, 3-stage, occ 2   <-- new
//  - AV:   fp16 1-term, occ 2 (R13-proven)
// B=8, N=2048, D_IN=512, H=1024, D_EMB=512, D_ATTN=256
// ============================================================================

#define B_   8
#define N_   2048
#define DIN  512
#define H_   1024
#define DEMB 512
#define DATT 256
#define M_   (B_ * N_)   // 16384

typedef __nv_bfloat16 bf16;

// ------------------------- device scratch (no allocs) ----------------------
__device__ __align__(16) bf16 g_xh[(size_t)M_ * DIN],          g_xl[(size_t)M_ * DIN];
__device__ __align__(16) __half g_xf[(size_t)M_ * DIN];
__device__ __align__(16) bf16 g_Wk1Th[(size_t)H_ * DIN],       g_Wk1Tl[(size_t)H_ * DIN];
__device__ __align__(16) __half g_We1f[(size_t)H_ * DIN];
__device__ __align__(16) bf16 g_Wk2Th[(size_t)(2*DATT) * H_],  g_Wk2Tl[(size_t)(2*DATT) * H_];
__device__ __align__(16) __half g_We2f[(size_t)DEMB * H_];
__device__ __align__(16) bf16 g_hh[(size_t)M_ * H_],           g_hl[(size_t)M_ * H_];
__device__ __align__(16) __half g_hf[(size_t)M_ * H_];
__device__ __align__(16) __half g_eTh[(size_t)B_ * DEMB * N_];
__device__ __align__(16) bf16 g_kqh[(size_t)M_ * (2*DATT)],    g_kql[(size_t)M_ * (2*DATT)];
__device__ __align__(16) float g_scores[(size_t)B_ * N_ * N_];
__device__ __align__(16) __half g_Af[(size_t)B_ * N_ * N_];

// ------------------------- helpers -----------------------------------------
__device__ __forceinline__ uint32_t smem_u32(const void* p) {
    uint32_t a;
    asm("{ .reg .u64 t; cvta.to.shared.u64 t, %1; cvt.u32.u64 %0, t; }"
        : "=r"(a) : "l"(p));
    return a;
}

__device__ __forceinline__ uint32_t pack2(bf16 a, bf16 b) {
    return (uint32_t)__bfloat16_as_ushort(a) | ((uint32_t)__bfloat16_as_ushort(b) << 16);
}
__device__ __forceinline__ uint32_t pack2h(__half a, __half b) {
    return (uint32_t)__half_as_ushort(a) | ((uint32_t)__half_as_ushort(b) << 16);
}
__device__ __forceinline__ void split1(float v, bf16& h, bf16& l) {
    h = __float2bfloat16(v);
    l = __float2bfloat16(v - __bfloat162float(h));
}

#define LDSM4(r0, r1, r2, r3, addr) \
    asm volatile("ldmatrix.sync.aligned.m8n8.x4.shared.b16 {%0,%1,%2,%3}, [%4];" \
        : "=r"(r0), "=r"(r1), "=r"(r2), "=r"(r3) : "r"(addr))

__device__ __forceinline__ void mma16816(float* d, const uint32_t* a, const uint32_t* b) {
    asm volatile(
        "mma.sync.aligned.m16n8k16.row.col.f32.bf16.bf16.f32 "
        "{%0,%1,%2,%3}, {%4,%5,%6,%7}, {%8,%9}, {%0,%1,%2,%3};"
        : "+f"(d[0]), "+f"(d[1]), "+f"(d[2]), "+f"(d[3])
        : "r"(a[0]), "r"(a[1]), "r"(a[2]), "r"(a[3]), "r"(b[0]), "r"(b[1]));
}
__device__ __forceinline__ void mma16816h(float* d, const uint32_t* a, const uint32_t* b) {
    asm volatile(
        "mma.sync.aligned.m16n8k16.row.col.f32.f16.f16.f32 "
        "{%0,%1,%2,%3}, {%4,%5,%6,%7}, {%8,%9}, {%0,%1,%2,%3};"
        : "+f"(d[0]), "+f"(d[1]), "+f"(d[2]), "+f"(d[3])
        : "r"(a[0]), "r"(a[1]), "r"(a[2]), "r"(a[3]), "r"(b[0]), "r"(b[1]));
}

#define CP_ASYNC16(dst, src) \
    asm volatile("cp.async.cg.shared.global [%0], [%1], 16;" :: "r"(dst), "l"(src))
#define CP_COMMIT() asm volatile("cp.async.commit_group;" ::: "memory")

// tile loader: 128 rows x 64 x 2B, XOR swizzle (chunk c of row r at c ^ (r&7))
__device__ __forceinline__ void load_tile(const bf16* __restrict__ g, int ld,
                                          uint32_t sm, int tid) {
#pragma unroll
    for (int i = 0; i < 4; i++) {
        int idx = i * 256 + tid;
        int r = idx >> 3;
        int c = idx & 7;
        const bf16* src = g + (size_t)r * ld + c * 8;
        uint32_t dst = sm + (uint32_t)(r * 128 + ((c ^ (r & 7)) << 4));
        CP_ASYNC16(dst, src);
    }
}

#define STAGE_SZ 65536              // 4 tiles x 16KB
#define SMEM_SZ  (3 * STAGE_SZ)     // 196608, 1 CTA/SM
#define STAGE_1T 32768              // 2 tiles (A + B single)
#define SMEM_1T  (3 * STAGE_1T)     // 98304, 2 CTAs/SM

// ============================================================================
// Split-bf16 GEMM (3-term), BK=64, 3-stage, acc-major (R9-proven).
// OMODE: 0 = split bf16 row-major;  2 = fp32 row-major (batch stride sC)
// ============================================================================
template <int KITERS, bool RELU, bool HAS_BIAS, int OMODE>
__global__ __launch_bounds__(256, 1) void mma_gemm(
    const bf16* __restrict__ Ah, const bf16* __restrict__ Al, int lda, size_t sA,
    const bf16* __restrict__ Bh, const bf16* __restrict__ Bl, int ldb, size_t sB,
    const float* __restrict__ bias,
    void* outHi, void* outLo, int ldc, size_t sC)
{
    extern __shared__ char smem[];
    const uint32_t sbase = smem_u32(smem);
    const int tid = threadIdx.x;
    const int lane = tid & 31, w = tid >> 5;
    const int wm = w & 1, wn = w >> 1;
    const int row0 = blockIdx.y * 128, col0 = blockIdx.x * 128, bz = blockIdx.z;

    const bf16* gAh = Ah + (size_t)bz * sA + (size_t)row0 * lda;
    const bf16* gAl = Al + (size_t)bz * sA + (size_t)row0 * lda;
    const bf16* gBh = Bh + (size_t)bz * sB + (size_t)col0 * ldb;
    const bf16* gBl = Bl + (size_t)bz * sB + (size_t)col0 * ldb;

    const int ra  = wm * 64 + (lane & 15);
    const int ca  = lane >> 4;
    const int rsa = ra & 7;
    const int rb  = wn * 32 + (lane & 7) + ((lane >> 4) & 1) * 8;
    const int cb  = (lane >> 3) & 1;
    const int rsb = rb & 7;

    float acc[4][4][4];
#pragma unroll
    for (int i = 0; i < 4; i++)
#pragma unroll
        for (int j = 0; j < 4; j++)
#pragma unroll
            for (int q = 0; q < 4; q++) acc[i][j][q] = 0.f;

    auto issue = [&](int s, int kt) {
        const size_t ko = (size_t)kt * 64;
        const uint32_t sb = sbase + s * STAGE_SZ;
        load_tile(gAh + ko, lda, sb,             tid);
        load_tile(gAl + ko, lda, sb + 16384,     tid);
        load_tile(gBh + ko, ldb, sb + 32768,     tid);
        load_tile(gBl + ko, ldb, sb + 49152,     tid);
        CP_COMMIT();
    };

    issue(0, 0);
    issue(1, 1);

    for (int kt = 0; kt < KITERS; kt++) {
        if (kt + 1 < KITERS) asm volatile("cp.async.wait_group 1;" ::: "memory");
        else                 asm volatile("cp.async.wait_group 0;" ::: "memory");
        __syncthreads();
        if (kt + 2 < KITERS) issue((kt + 2) % 3, kt + 2);
        const uint32_t sb  = sbase + (kt % 3) * STAGE_SZ;
        const uint32_t aHb = sb, aLb = sb + 16384, bHb = sb + 32768, bLb = sb + 49152;

#pragma unroll
        for (int ks = 0; ks < 4; ks++) {
            uint32_t ah[4][4], alr[4][4], bh[2][4], blr[2][4];
#pragma unroll
            for (int i = 0; i < 4; i++) {
                uint32_t off = (uint32_t)((ra + i * 16) * 128 +
                               ((((ks << 1) | ca) ^ rsa) << 4));
                LDSM4(ah[i][0],  ah[i][1],  ah[i][2],  ah[i][3],  aHb + off);
                LDSM4(alr[i][0], alr[i][1], alr[i][2], alr[i][3], aLb + off);
            }
#pragma unroll
            for (int jp = 0; jp < 2; jp++) {
                uint32_t off = (uint32_t)((rb + jp * 16) * 128 +
                               ((((ks << 1) | cb) ^ rsb) << 4));
                LDSM4(bh[jp][0],  bh[jp][1],  bh[jp][2],  bh[jp][3],  bHb + off);
                LDSM4(blr[jp][0], blr[jp][1], blr[jp][2], blr[jp][3], bLb + off);
            }
#pragma unroll
            for (int i = 0; i < 4; i++)
#pragma unroll
                for (int j = 0; j < 4; j++) {
                    const uint32_t* bph = &bh[j >> 1][(j & 1) << 1];
                    const uint32_t* bpl = &blr[j >> 1][(j & 1) << 1];
                    mma16816(acc[i][j], ah[i], bph);
                    mma16816(acc[i][j], ah[i], bpl);
                    mma16816(acc[i][j], alr[i], bph);
                }
        }
    }

#pragma unroll
    for (int j = 0; j < 4; j++) {
        const int cbj = col0 + wn * 32 + j * 8 + ((lane & 3) << 1);
        const float bb0 = HAS_BIAS ? bias[cbj] : 0.f;
        const float bb1 = HAS_BIAS ? bias[cbj + 1] : 0.f;
#pragma unroll
        for (int i = 0; i < 4; i++)
#pragma unroll
            for (int rep = 0; rep < 2; rep++) {
                const int rg = row0 + wm * 64 + i * 16 + (lane >> 2) + rep * 8;
                float v0 = acc[i][j][rep * 2 + 0] + bb0;
                float v1 = acc[i][j][rep * 2 + 1] + bb1;
                if (RELU) { v0 = fmaxf(v0, 0.f); v1 = fmaxf(v1, 0.f); }
                if (OMODE == 2) {
                    float2* p = (float2*)((float*)outHi + (size_t)bz * sC +
                                          (size_t)rg * ldc + cbj);
                    *p = make_float2(v0, v1);
                } else {
                    bf16 h0, l0, h1, l1;
                    split1(v0, h0, l0); split1(v1, h1, l1);
                    *(uint32_t*)((bf16*)outHi + (size_t)rg * ldc + cbj) = pack2(h0, h1);
                    *(uint32_t*)((bf16*)outLo + (size_t)rg * ldc + cbj) = pack2(l0, l1);
                }
            }
    }
}

// ============================================================================
// 1-term fp16 GEMM (AV structure: 2 tiles/stage, 3-stage, occ 2).
// EPI: 0 = fp32 row-major (batched, sA/sB/sC used)          [AV]
//      1 = fp16 row-major + bias + relu                      [h1]
//      2 = fp16 TRANSPOSED into embsT[b][DEMB][N_] + bias    [embs]
// ============================================================================
template <int KITERS, int EPI>
__global__ __launch_bounds__(256, 2) void mma_1t(
    const __half* __restrict__ Af, int lda, size_t sA,
    const __half* __restrict__ Bf, int ldb, size_t sB,
    const float* __restrict__ bias,
    void* outP, int ldc, size_t sC)
{
    extern __shared__ char smem[];
    const uint32_t sbase = smem_u32(smem);
    const int tid = threadIdx.x;
    const int lane = tid & 31, w = tid >> 5;
    const int wm = w & 1, wn = w >> 1;
    const int row0 = blockIdx.y * 128, col0 = blockIdx.x * 128, bz = blockIdx.z;

    const bf16* gA = (const bf16*)(Af + (size_t)bz * sA + (size_t)row0 * lda);
    const bf16* gB = (const bf16*)(Bf + (size_t)bz * sB + (size_t)col0 * ldb);

    const int ra  = wm * 64 + (lane & 15);
    const int ca  = lane >> 4;
    const int rsa = ra & 7;
    const int rb  = wn * 32 + (lane & 7) + ((lane >> 4) & 1) * 8;
    const int cb  = (lane >> 3) & 1;
    const int rsb = rb & 7;

    float acc[4][4][4];
#pragma unroll
    for (int i = 0; i < 4; i++)
#pragma unroll
        for (int j = 0; j < 4; j++)
#pragma unroll
            for (int q = 0; q < 4; q++) acc[i][j][q] = 0.f;

    auto issue = [&](int s, int kt) {
        const size_t ko = (size_t)kt * 64;
        const uint32_t sb = sbase + s * STAGE_1T;
        load_tile(gA + ko, lda, sb,         tid);
        load_tile(gB + ko, ldb, sb + 16384, tid);
        CP_COMMIT();
    };

    issue(0, 0);
    issue(1, 1);

    for (int kt = 0; kt < KITERS; kt++) {
        if (kt + 1 < KITERS) asm volatile("cp.async.wait_group 1;" ::: "memory");
        else                 asm volatile("cp.async.wait_group 0;" ::: "memory");
        __syncthreads();
        if (kt + 2 < KITERS) issue((kt + 2) % 3, kt + 2);
        const uint32_t sb = sbase + (kt % 3) * STAGE_1T;
        const uint32_t aB = sb, bB = sb + 16384;

#pragma unroll
        for (int ks = 0; ks < 4; ks++) {
            uint32_t ah[4][4], bh[2][4];
#pragma unroll
            for (int i = 0; i < 4; i++) {
                uint32_t off = (uint32_t)((ra + i * 16) * 128 +
                               ((((ks << 1) | ca) ^ rsa) << 4));
                LDSM4(ah[i][0], ah[i][1], ah[i][2], ah[i][3], aB + off);
            }
#pragma unroll
            for (int jp = 0; jp < 2; jp++) {
                uint32_t off = (uint32_t)((rb + jp * 16) * 128 +
                               ((((ks << 1) | cb) ^ rsb) << 4));
                LDSM4(bh[jp][0], bh[jp][1], bh[jp][2], bh[jp][3], bB + off);
            }
#pragma unroll
            for (int i = 0; i < 4; i++)
#pragma unroll
                for (int j = 0; j < 4; j++)
                    mma16816h(acc[i][j], ah[i], &bh[j >> 1][(j & 1) << 1]);
        }
    }

    if (EPI == 0) {
        float* out = (float*)outP;
#pragma unroll
        for (int j = 0; j < 4; j++) {
            const int cbj = col0 + wn * 32 + j * 8 + ((lane & 3) << 1);
#pragma unroll
            for (int i = 0; i < 4; i++)
#pragma unroll
                for (int rep = 0; rep < 2; rep++) {
                    const int rg = row0 + wm * 64 + i * 16 + (lane >> 2) + rep * 8;
                    float2* p = (float2*)(out + (size_t)bz * sC + (size_t)rg * ldc + cbj);
                    *p = make_float2(acc[i][j][rep * 2 + 0], acc[i][j][rep * 2 + 1]);
                }
        }
    } else if (EPI == 1) {
        __half* out = (__half*)outP;
#pragma unroll
        for (int j = 0; j < 4; j++) {
            const int cbj = col0 + wn * 32 + j * 8 + ((lane & 3) << 1);
            const float bb0 = bias[cbj];
            const float bb1 = bias[cbj + 1];
#pragma unroll
            for (int i = 0; i < 4; i++)
#pragma unroll
                for (int rep = 0; rep < 2; rep++) {
                    const int rg = row0 + wm * 64 + i * 16 + (lane >> 2) + rep * 8;
                    float v0 = fmaxf(acc[i][j][rep * 2 + 0] + bb0, 0.f);
                    float v1 = fmaxf(acc[i][j][rep * 2 + 1] + bb1, 0.f);
                    *(uint32_t*)(out + (size_t)rg * ldc + cbj) =
                        pack2h(__float2half_rn(v0), __float2half_rn(v1));
                }
        }
    } else {
        // transposed single fp16 write into embsT, with bias
        __syncthreads();   // mainloop LDSM readers done before buf reuse
        float* buf = reinterpret_cast<float*>(smem) + w * 2112;   // 64 x 33
#pragma unroll
        for (int i = 0; i < 4; i++)
#pragma unroll
            for (int j = 0; j < 4; j++)
#pragma unroll
                for (int rep = 0; rep < 2; rep++) {
                    const int ml = i * 16 + (lane >> 2) + rep * 8;
                    const int nl = j * 8 + ((lane & 3) << 1);
                    buf[ml * 33 + nl]     = acc[i][j][rep * 2 + 0];
                    buf[ml * 33 + nl + 1] = acc[i][j][rep * 2 + 1];
                }
        __syncwarp();
        __half* out = (__half*)outP;
        const int colsel = lane >> 3;
        const int seg    = lane & 7;
        const int rowg0 = row0 + wm * 64;
        const int b = rowg0 >> 11, pos = rowg0 & (N_ - 1);
#pragma unroll
        for (int cp = 0; cp < 8; cp++) {
            const int csub = cp * 4 + colsel;
            const int colg = col0 + wn * 32 + csub;
            const float fb = bias[colg];
            uint32_t ph[4];
#pragma unroll
            for (int q = 0; q < 4; q++) {
                float v0 = buf[(seg * 8 + 2 * q) * 33 + csub] + fb;
                float v1 = buf[(seg * 8 + 2 * q + 1) * 33 + csub] + fb;
                ph[q] = pack2h(__float2half_rn(v0), __float2half_rn(v1));
            }
            const size_t addr = ((size_t)b * DEMB + colg) * (size_t)N_ + pos + seg * 8;
            *(uint4*)(out + addr) = make_uint4(ph[0], ph[1], ph[2], ph[3]);
        }
    }
}

// ============================================================================
// prep kernels
// ============================================================================
// x -> bf16 hi/lo (kq path) + fp16 single (embs path)
__global__ __launch_bounds__(256) void k_split(const float* __restrict__ s,
                                               bf16* __restrict__ h,
                                               bf16* __restrict__ l,
                                               __half* __restrict__ f, size_t n) {
    size_t i = ((size_t)blockIdx.x * 256 + threadIdx.x) * 4;
    if (i >= n) return;
    float4 v = *reinterpret_cast<const float4*>(s + i);
    bf16 h0, l0, h1, l1, h2, l2, h3, l3;
    split1(v.x, h0, l0); split1(v.y, h1, l1);
    split1(v.z, h2, l2); split1(v.w, h3, l3);
    *reinterpret_cast<uint2*>(h + i) = make_uint2(pack2(h0, h1), pack2(h2, h3));
    *reinterpret_cast<uint2*>(l + i) = make_uint2(pack2(l0, l1), pack2(l2, l3));
    *reinterpret_cast<uint2*>(f + i) = make_uint2(
        pack2h(__float2half_rn(v.x), __float2half_rn(v.y)),
        pack2h(__float2half_rn(v.z), __float2half_rn(v.w)));
}

// z=0: We1 -> fp16 single; z=1: Wk1 -> bf16 split
// z=2: We2 -> fp16 single; z=3: Wk2 -> bf16 split
__global__ __launch_bounds__(256) void k_splitT_all(
    const float* __restrict__ We1, const float* __restrict__ Wk1,
    const float* __restrict__ We2, const float* __restrict__ Wk2,
    __half* __restrict__ We1f,
    bf16* __restrict__ Wk1Th, bf16* __restrict__ Wk1Tl,
    __half* __restrict__ We2f,
    bf16* __restrict__ Wk2Th, bf16* __restrict__ Wk2Tl)
{
    const int z = blockIdx.z;
    const float* W; int K, Nc;
    if (z == 0)      { W = We1; K = DIN; Nc = H_; }
    else if (z == 1) { W = Wk1; K = DIN; Nc = H_; }
    else if (z == 2) { W = We2; K = H_;  Nc = DEMB; }
    else             { W = Wk2; K = H_;  Nc = 2 * DATT; }
    const int k0 = blockIdx.x * 32, n0 = blockIdx.y * 32;
    if (k0 >= K || n0 >= Nc) return;

    __shared__ float t[32][33];
    const int c = threadIdx.x & 31, r = threadIdx.x >> 5;
#pragma unroll
    for (int i = 0; i < 4; i++)
        t[i * 8 + r][c] = W[(size_t)(k0 + i * 8 + r) * Nc + n0 + c];
    __syncthreads();
#pragma unroll
    for (int i = 0; i < 4; i++) {
        const int n = n0 + i * 8 + r;
        const float v = t[c][i * 8 + r];
        const size_t idx = (size_t)n * K + k0 + c;
        if (z == 0)      We1f[idx] = __float2half_rn(v);
        else if (z == 2) We2f[idx] = __float2half_rn(v);
        else if (z == 1) { bf16 h, l; split1(v, h, l); Wk1Th[idx] = h; Wk1Tl[idx] = l; }
        else             { bf16 h, l; split1(v, h, l); Wk2Th[idx] = h; Wk2Tl[idx] = l; }
    }
}

// ============================================================================
// softmax over rows of scores (fp32), output single fp16
// ============================================================================
__global__ __launch_bounds__(256) void k_softmax(const float* __restrict__ S,
                                                 __half* __restrict__ Af) {
    const size_t row = blockIdx.x;
    const float4* r = reinterpret_cast<const float4*>(S + row * N_);
    const int tid = threadIdx.x;
    __shared__ float red[256];

    float4 a = r[tid], b = r[tid + 256];
    float m = fmaxf(fmaxf(fmaxf(a.x, a.y), fmaxf(a.z, a.w)),
                    fmaxf(fmaxf(b.x, b.y), fmaxf(b.z, b.w)));
    red[tid] = m; __syncthreads();
#pragma unroll
    for (int s = 128; s > 0; s >>= 1) {
        if (tid < s) red[tid] = fmaxf(red[tid], red[tid + s]);
        __syncthreads();
    }
    m = red[0]; __syncthreads();

    a.x = __expf(a.x - m); a.y = __expf(a.y - m);
    a.z = __expf(a.z - m); a.w = __expf(a.w - m);
    b.x = __expf(b.x - m); b.y = __expf(b.y - m);
    b.z = __expf(b.z - m); b.w = __expf(b.w - m);
    red[tid] = (a.x + a.y + a.z + a.w) + (b.x + b.y + b.z + b.w);
    __syncthreads();
#pragma unroll
    for (int s = 128; s > 0; s >>= 1) {
        if (tid < s) red[tid] += red[tid + s];
        __syncthreads();
    }
    const float inv = 1.f / red[0];

    uint32_t q0 = pack2h(__float2half_rn(a.x * inv), __float2half_rn(a.y * inv));
    uint32_t q1 = pack2h(__float2half_rn(a.z * inv), __float2half_rn(a.w * inv));
    uint32_t q2 = pack2h(__float2half_rn(b.x * inv), __float2half_rn(b.y * inv));
    uint32_t q3 = pack2h(__float2half_rn(b.z * inv), __float2half_rn(b.w * inv));
    uint2* o = reinterpret_cast<uint2*>(Af + row * N_);
    o[tid]       = make_uint2(q0, q1);
    o[tid + 256] = make_uint2(q2, q3);
}

// ============================================================================
extern "C" void kernel_launch(void* const* d_in, const int* in_sizes, int n_in,
                              void* d_out, int out_size)
{
    const float* x   = (const float*)d_in[0];
    const float* We1 = (const float*)d_in[1];
    const float* be1 = (const float*)d_in[2];
    const float* We2 = (const float*)d_in[3];
    const float* be2 = (const float*)d_in[4];
    const float* Wk1 = (const float*)d_in[5];
    const float* bk1 = (const float*)d_in[6];
    const float* Wk2 = (const float*)d_in[7];
    const float* bk2 = (const float*)d_in[8];
    float* out = (float*)d_out;

    bf16 *xh, *xl, *Wk1Th, *Wk1Tl, *Wk2Th, *Wk2Tl, *hh, *hl, *kqh, *kql;
    __half *xf, *We1f, *We2f, *hf, *eTh, *Af;
    float *scores;
    cudaGetSymbolAddress((void**)&xh, g_xh);       cudaGetSymbolAddress((void**)&xl, g_xl);
    cudaGetSymbolAddress((void**)&xf, g_xf);
    cudaGetSymbolAddress((void**)&Wk1Th, g_Wk1Th); cudaGetSymbolAddress((void**)&Wk1Tl, g_Wk1Tl);
    cudaGetSymbolAddress((void**)&We1f, g_We1f);
    cudaGetSymbolAddress((void**)&Wk2Th, g_Wk2Th); cudaGetSymbolAddress((void**)&Wk2Tl, g_Wk2Tl);
    cudaGetSymbolAddress((void**)&We2f, g_We2f);
    cudaGetSymbolAddress((void**)&hh, g_hh);       cudaGetSymbolAddress((void**)&hl, g_hl);
    cudaGetSymbolAddress((void**)&hf, g_hf);
    cudaGetSymbolAddress((void**)&eTh, g_eTh);
    cudaGetSymbolAddress((void**)&kqh, g_kqh);     cudaGetSymbolAddress((void**)&kql, g_kql);
    cudaGetSymbolAddress((void**)&scores, g_scores);
    cudaGetSymbolAddress((void**)&Af, g_Af);

    cudaFuncSetAttribute(mma_gemm<8,  true,  true,  0>, cudaFuncAttributeMaxDynamicSharedMemorySize, SMEM_SZ);
    cudaFuncSetAttribute(mma_gemm<16, false, true,  0>, cudaFuncAttributeMaxDynamicSharedMemorySize, SMEM_SZ);
    cudaFuncSetAttribute(mma_gemm<4,  false, false, 2>, cudaFuncAttributeMaxDynamicSharedMemorySize, SMEM_SZ);
    cudaFuncSetAttribute(mma_1t<8,  1>, cudaFuncAttributeMaxDynamicSharedMemorySize, SMEM_1T);
    cudaFuncSetAttribute(mma_1t<16, 2>, cudaFuncAttributeMaxDynamicSharedMemorySize, SMEM_1T);
    cudaFuncSetAttribute(mma_1t<32, 0>, cudaFuncAttributeMaxDynamicSharedMemorySize, SMEM_1T);

    // ---- prep ----------------------------------------------------------------
    k_split<<<(M_ * DIN / 4 + 255) / 256, 256>>>(x, xh, xl, xf, (size_t)M_ * DIN);
    k_splitT_all<<<dim3(32, 32, 4), 256>>>(We1, Wk1, We2, Wk2,
                                           We1f, Wk1Th, Wk1Tl, We2f, Wk2Th, Wk2Tl);

    // ---- 1) h_k = relu(x @ Wk1 + bk1)  (bf16 3-term) --------------------------
    mma_gemm<8, true, true, 0><<<dim3(H_ / 128, M_ / 128, 1), 256, SMEM_SZ>>>(
        xh, xl, DIN, 0, Wk1Th, Wk1Tl, DIN, 0, bk1,
        hh, hl, H_, 0);

    // ---- 2) h_f = relu(x_f @ We1_f + be1)  (fp16 1-term, occ 2) ---------------
    mma_1t<8, 1><<<dim3(H_ / 128, M_ / 128, 1), 256, SMEM_1T>>>(
        xf, DIN, 0, We1f, DIN, 0, be1, hf, H_, 0);

    // ---- 3) kq = h_k @ Wk2 + bk2  (bf16 3-term) -------------------------------
    mma_gemm<16, false, true, 0><<<dim3((2 * DATT) / 128, M_ / 128, 1), 256, SMEM_SZ>>>(
        hh, hl, H_, 0, Wk2Th, Wk2Tl, H_, 0, bk2,
        kqh, kql, 2 * DATT, 0);

    // ---- 4) embsT = (h_f @ We2_f + be2)^T  (fp16 1-term, occ 2) ---------------
    mma_1t<16, 2><<<dim3(DEMB / 128, M_ / 128, 1), 256, SMEM_1T>>>(
        hf, H_, 0, We2f, H_, 0, be2, eTh, 0, 0);

    // ---- 5) scores_b = Q_b @ K_b^T  (bf16 3-term) -----------------------------
    mma_gemm<4, false, false, 2><<<dim3(N_ / 128, N_ / 128, B_), 256, SMEM_SZ>>>(
        kqh + DATT, kql + DATT, 2 * DATT, (size_t)N_ * 2 * DATT,
        kqh,        kql,        2 * DATT, (size_t)N_ * 2 * DATT,
        nullptr, scores, nullptr, N_, (size_t)N_ * N_);

    // ---- 6) softmax -> single fp16 A ------------------------------------------
    k_softmax<<<B_ * N_, 256>>>(scores, Af);

    // ---- 7) out_b = A_b @ embs_b  (fp16 1-term, occ 2) ------------------------
    mma_1t<32, 0><<<dim3(DEMB / 128, N_ / 128, B_), 256, SMEM_1T>>>(
        Af, N_, (size_t)N_ * N_,
        eTh, N_, (size_t)DEMB * N_,
        nullptr, out, DEMB, (size_t)N_ * DEMB);
}